// round 12
// baseline (speedup 1.0000x reference)
#include <cuda_runtime.h>
#include <cuda_bf16.h>
#include <math.h>
#include <stdint.h>

#define TOK   100352
#define CD    192
#define NWIN  2048
#define NHEAD 6
#define HDIM  32
#define HID   768

typedef __nv_bfloat16 bf16;

// ---------------- scratch ----------------------------------------------------
__device__ bf16  g_xwb [(size_t)TOK * CD];
__device__ bf16  g_qkvb[(size_t)TOK * 3 * CD];
__device__ bf16  g_attb[(size_t)TOK * CD];
__device__ float g_x2  [(size_t)TOK * CD];
__device__ bf16  g_xn2b[(size_t)TOK * CD];
__device__ bf16  g_hb  [(size_t)TOK * HID];
__device__ bf16  g_wqkv[576 * CD];
__device__ bf16  g_wp  [CD * CD];
__device__ bf16  g_wf1 [HID * CD];
__device__ bf16  g_wf2 [CD * HID];
__device__ float g_bias6[NHEAD * 49 * 49];

// ---------------- fused convert + bias expand -------------------------------
#define N_QKVW (576 * CD)
#define N_PW   (CD * CD)
#define N_F1W  (HID * CD)
#define N_F2W  (CD * HID)
#define N_WTOT (N_QKVW + N_PW + N_F1W + N_F2W)
#define N_BIAS (NHEAD * 49 * 49)

__global__ void prep_kernel(const float* __restrict__ qkvw, const float* __restrict__ pw,
                            const float* __restrict__ f1w, const float* __restrict__ f2w,
                            const float* __restrict__ tab, const int* __restrict__ ridx)
{
    int i = blockIdx.x * 256 + threadIdx.x;
    if (i < N_QKVW) { g_wqkv[i] = __float2bfloat16(qkvw[i]); return; }
    i -= N_QKVW;
    if (i < N_PW)   { g_wp[i]   = __float2bfloat16(pw[i]);   return; }
    i -= N_PW;
    if (i < N_F1W)  { g_wf1[i]  = __float2bfloat16(f1w[i]);  return; }
    i -= N_F1W;
    if (i < N_F2W)  { g_wf2[i]  = __float2bfloat16(f2w[i]);  return; }
    i -= N_F2W;
    if (i < N_BIAS) {
        int h = i / 2401, nm = i - h * 2401;
        g_bias6[i] = tab[ridx[nm] * NHEAD + h];
    }
}

// ---------------- LayerNorm (LN1 + shift + gather): one warp per token -------
__global__ __launch_bounds__(256)
void ln_warp(const float* __restrict__ xin,
             const float* __restrict__ gamma,
             const float* __restrict__ beta,
             bf16* __restrict__ out)
{
    int m = blockIdx.x * 8 + (threadIdx.x >> 5);
    int lane = threadIdx.x & 31;
    int w = m / 49, n = m - w * 49;
    int bb = w >> 6, rem = w & 63, hb = rem >> 3, wb = rem & 7;
    int r = n / 7, cn = n - r * 7;
    int hh = hb * 7 + r + 3;  if (hh >= 56) hh -= 56;
    int ww = wb * 7 + cn + 3; if (ww >= 56) ww -= 56;
    size_t src = ((size_t)bb * 3136 + hh * 56 + ww);

    const float* p = xin + src * CD;
    float v[6];
    float s = 0.f, s2 = 0.f;
    #pragma unroll
    for (int i = 0; i < 6; i++) {
        v[i] = p[lane + 32 * i];
        s += v[i]; s2 += v[i] * v[i];
    }
    #pragma unroll
    for (int o = 16; o > 0; o >>= 1) {
        s  += __shfl_xor_sync(0xFFFFFFFFu, s,  o);
        s2 += __shfl_xor_sync(0xFFFFFFFFu, s2, o);
    }
    float mean = s * (1.f / CD);
    float var  = s2 * (1.f / CD) - mean * mean;
    float inv  = rsqrtf(var + 1e-5f);
    bf16* o = out + (size_t)m * CD;
    #pragma unroll
    for (int i = 0; i < 6; i++) {
        int c = lane + 32 * i;
        o[c] = __float2bfloat16((v[i] - mean) * inv * gamma[c] + beta[c]);
    }
}

// ---------------- helpers ----------------------------------------------------
__device__ __forceinline__ void cp16(uint32_t dst, const void* src) {
    asm volatile("cp.async.cg.shared.global [%0], [%1], 16;\n" :: "r"(dst), "l"(src));
}
__device__ __forceinline__ void cp16z(uint32_t dst, const void* src, int sz) {
    asm volatile("cp.async.cg.shared.global [%0], [%1], 16, %2;\n" :: "r"(dst), "l"(src), "r"(sz));
}
__device__ __forceinline__ void ldsm_x4(uint32_t* r, uint32_t addr) {
    asm volatile("ldmatrix.sync.aligned.m8n8.x4.shared.b16 {%0,%1,%2,%3}, [%4];\n"
                 : "=r"(r[0]), "=r"(r[1]), "=r"(r[2]), "=r"(r[3]) : "r"(addr));
}
__device__ __forceinline__ void ldsm_x4t(uint32_t* r, uint32_t addr) {
    asm volatile("ldmatrix.sync.aligned.m8n8.x4.trans.shared.b16 {%0,%1,%2,%3}, [%4];\n"
                 : "=r"(r[0]), "=r"(r[1]), "=r"(r[2]), "=r"(r[3]) : "r"(addr));
}
__device__ __forceinline__ void mma16816(float* d, const uint32_t* a, const uint32_t* b) {
    asm volatile(
        "mma.sync.aligned.m16n8k16.row.col.f32.bf16.bf16.f32 "
        "{%0,%1,%2,%3}, {%4,%5,%6,%7}, {%8,%9}, {%0,%1,%2,%3};\n"
        : "+f"(d[0]), "+f"(d[1]), "+f"(d[2]), "+f"(d[3])
        : "r"(a[0]), "r"(a[1]), "r"(a[2]), "r"(a[3]), "r"(b[0]), "r"(b[1]));
}
__device__ __forceinline__ uint32_t packbf(float a, float b) {
    __nv_bfloat162 t = __floats2bfloat162_rn(a, b);
    return *(uint32_t*)&t;
}
__device__ __forceinline__ uint32_t smem_u32(const void* p) {
    return (uint32_t)__cvta_generic_to_shared(p);
}

// ---------------- bf16 GEMM: C[M,N] = A[M,K] @ B[N,K]^T + bias --------------
// Block tile 128(M) x 192(N), BK=64, 2-stage double buffer, 512 threads.
// 16 warps: 4(M) x 4(N); warp tile 32(M) x 48(N); mma.m16n8k16, 4 kk sub-iters.
// Rows are 128B (full SW128 swizzle: chunk c ^ (r&7)).
// MODE 0: bf16 out (qkv) | 1: GELU bf16 (fc1) | 2: +aux fp32 (fc2 -> d_out)
// MODE 3: proj: scatter + residual -> x2 (fp32) AND fused LN2 -> lnOut (bf16)
#define GBM 128
#define GBN 192
#define GBK 64
#define NTH 512
#define SA_STG 16384           // 128 rows * 128B
#define SB_STG 24576           // 192 rows * 128B
#define OFF_A(s) ((s) * SA_STG)
#define OFF_B(s) (2 * SA_STG + (s) * SB_STG)
#define OFF_RED  (2 * SA_STG + 2 * SB_STG)     // 81920
#define GSM_TOT  (OFF_RED + 4096)              // 86016

template <int MODE, typename OutT>
__global__ __launch_bounds__(NTH, 1)
void gemm_n192(const bf16* __restrict__ A, const bf16* __restrict__ B,
               const float* __restrict__ bias, const float* __restrict__ aux,
               OutT* __restrict__ Cout, int N, int K,
               const float* __restrict__ lnG, const float* __restrict__ lnB,
               bf16* __restrict__ lnOut)
{
    extern __shared__ __align__(128) char smem[];
    uint32_t sb = smem_u32(smem);
    float* red = (float*)(smem + OFF_RED);

    int tid = threadIdx.x;
    int warp = tid >> 5, lane = tid & 31;
    int warpM = warp & 3;              // rows warpM*32
    int warpN = warp >> 2;             // cols warpN*48
    int row0 = blockIdx.y * GBM;
    int col0 = blockIdx.x * GBN;

    float acc[2][6][4];
    #pragma unroll
    for (int mt = 0; mt < 2; mt++)
        #pragma unroll
        for (int nt = 0; nt < 6; nt++)
            #pragma unroll
            for (int i = 0; i < 4; i++) acc[mt][nt][i] = 0.f;

    const int nk = K / GBK;

    auto stage = [&](int s, int k0) {
        #pragma unroll
        for (int j = 0; j < 2; j++) {                   // A: 1024 x 16B
            int idx = tid + j * NTH;
            int r = idx >> 3, c = idx & 7;
            int sw = c ^ (r & 7);
            cp16(sb + OFF_A(s) + r * 128 + sw * 16,
                 A + (size_t)(row0 + r) * K + k0 + c * 8);
        }
        #pragma unroll
        for (int j = 0; j < 3; j++) {                   // B: 1536 x 16B
            int idx = tid + j * NTH;
            int r = idx >> 3, c = idx & 7;
            int sw = c ^ (r & 7);
            cp16(sb + OFF_B(s) + r * 128 + sw * 16,
                 B + (size_t)(col0 + r) * K + k0 + c * 8);
        }
        asm volatile("cp.async.commit_group;\n" ::: "memory");
    };

    stage(0, 0);

    for (int it = 0; it < nk; it++) {
        if (it + 1 < nk) {
            stage((it + 1) & 1, (it + 1) * GBK);
            asm volatile("cp.async.wait_group 1;\n" ::: "memory");
        } else {
            asm volatile("cp.async.wait_group 0;\n" ::: "memory");
        }
        __syncthreads();
        uint32_t aB = sb + OFF_A(it & 1);
        uint32_t bB = sb + OFF_B(it & 1);
        #pragma unroll
        for (int kk = 0; kk < 4; kk++) {
            uint32_t afr[2][4], bfr[3][4];
            #pragma unroll
            for (int mt = 0; mt < 2; mt++) {
                int r = warpM * 32 + mt * 16 + (lane & 15);
                int c = kk * 2 + (lane >> 4);
                int sw = c ^ (r & 7);
                ldsm_x4(afr[mt], aB + r * 128 + sw * 16);
            }
            #pragma unroll
            for (int nb = 0; nb < 3; nb++) {
                int r = warpN * 48 + nb * 16 + ((lane >> 4) << 3) + (lane & 7);
                int c = kk * 2 + ((lane >> 3) & 1);
                int sw = c ^ (r & 7);
                ldsm_x4(bfr[nb], bB + r * 128 + sw * 16);
            }
            #pragma unroll
            for (int mt = 0; mt < 2; mt++)
                #pragma unroll
                for (int nt = 0; nt < 6; nt++)
                    mma16816(acc[mt][nt], afr[mt], &bfr[nt >> 1][(nt & 1) * 2]);
        }
        __syncthreads();
    }

    // ---- epilogue: bias (+aux/GELU), row targets ----
    int gr = lane >> 2, gc = lane & 3;
    size_t orows[2][2];
    #pragma unroll
    for (int mt = 0; mt < 2; mt++) {
        #pragma unroll
        for (int half = 0; half < 2; half++) {
            int row = row0 + warpM * 32 + mt * 16 + gr + half * 8;
            size_t orow = row;
            if (MODE == 3) {
                int w = row / 49, n = row - w * 49;
                int bb = w >> 6, rem = w & 63, hb = rem >> 3, wb = rem & 7;
                int r = n / 7, cn = n - r * 7;
                int hh = hb * 7 + r + 3;  if (hh >= 56) hh -= 56;
                int ww = wb * 7 + cn + 3; if (ww >= 56) ww -= 56;
                orow = ((size_t)bb * 3136 + hh * 56 + ww);
            }
            orows[mt][half] = orow;
            #pragma unroll
            for (int nt = 0; nt < 6; nt++) {
                int col = col0 + warpN * 48 + nt * 8 + gc * 2;
                float* d = &acc[mt][nt][half * 2];
                d[0] += bias[col];
                d[1] += bias[col + 1];
                if (MODE == 1) {
                    d[0] = 0.5f * d[0] * (1.f + erff(d[0] * 0.70710678118654752f));
                    d[1] = 0.5f * d[1] * (1.f + erff(d[1] * 0.70710678118654752f));
                } else if (MODE == 2) {
                    const float* ap = aux + (size_t)row * N + col;
                    d[0] += ap[0]; d[1] += ap[1];
                } else if (MODE == 3) {
                    const float* ap = aux + orow * CD + col;
                    d[0] += ap[0]; d[1] += ap[1];
                }
            }
        }
    }

    // ---- fused LN2 stats (MODE 3; BN=192 == full row) ----
    float mean[2][2], inv[2][2];
    if (MODE == 3) {
        #pragma unroll
        for (int mt = 0; mt < 2; mt++)
            #pragma unroll
            for (int half = 0; half < 2; half++) {
                float s = 0.f, q = 0.f;
                #pragma unroll
                for (int nt = 0; nt < 6; nt++) {
                    float v0 = acc[mt][nt][half * 2], v1 = acc[mt][nt][half * 2 + 1];
                    s += v0 + v1; q += v0 * v0 + v1 * v1;
                }
                s += __shfl_xor_sync(0xFFFFFFFFu, s, 1);
                s += __shfl_xor_sync(0xFFFFFFFFu, s, 2);
                q += __shfl_xor_sync(0xFFFFFFFFu, q, 1);
                q += __shfl_xor_sync(0xFFFFFFFFu, q, 2);
                if (gc == 0) {
                    int rl = warpM * 32 + mt * 16 + gr + half * 8;
                    red[rl * 4 + warpN] = s;
                    red[512 + rl * 4 + warpN] = q;
                }
            }
        __syncthreads();
        #pragma unroll
        for (int mt = 0; mt < 2; mt++)
            #pragma unroll
            for (int half = 0; half < 2; half++) {
                int rl = warpM * 32 + mt * 16 + gr + half * 8;
                float s = red[rl * 4] + red[rl * 4 + 1] + red[rl * 4 + 2] + red[rl * 4 + 3];
                float q = red[512 + rl * 4] + red[512 + rl * 4 + 1]
                        + red[512 + rl * 4 + 2] + red[512 + rl * 4 + 3];
                float mu = s * (1.f / CD);
                mean[mt][half] = mu;
                inv[mt][half]  = rsqrtf(q * (1.f / CD) - mu * mu + 1e-5f);
            }
    }

    // ---- stores ----
    #pragma unroll
    for (int mt = 0; mt < 2; mt++) {
        #pragma unroll
        for (int half = 0; half < 2; half++) {
            int row = row0 + warpM * 32 + mt * 16 + gr + half * 8;
            size_t orow = orows[mt][half];
            #pragma unroll
            for (int nt = 0; nt < 6; nt++) {
                int col = col0 + warpN * 48 + nt * 8 + gc * 2;
                float v0 = acc[mt][nt][half * 2], v1 = acc[mt][nt][half * 2 + 1];
                if (MODE == 0 || MODE == 1) {
                    *(uint32_t*)((bf16*)Cout + (size_t)row * N + col) = packbf(v0, v1);
                } else if (MODE == 2) {
                    *(float2*)((float*)Cout + (size_t)row * N + col) = make_float2(v0, v1);
                } else { // MODE 3
                    *(float2*)((float*)Cout + orow * CD + col) = make_float2(v0, v1);
                    float o0 = (v0 - mean[mt][half]) * inv[mt][half] * __ldg(lnG + col)
                             + __ldg(lnB + col);
                    float o1 = (v1 - mean[mt][half]) * inv[mt][half] * __ldg(lnG + col + 1)
                             + __ldg(lnB + col + 1);
                    *(uint32_t*)(lnOut + orow * CD + col) = packbf(o0, o1);
                }
            }
        }
    }
}

// ---------------- MMA attention: block = (window, head pair) ----------------
__global__ __launch_bounds__(256)
void attn_mma(const bf16* __restrict__ qkv,
              const float* __restrict__ bias6,
              bf16* __restrict__ out)
{
    int win = blockIdx.y;
    int hp  = blockIdx.x;
    int tid = threadIdx.x;
    int wg  = tid >> 7;
    int h   = hp * 2 + wg;
    int wgtid = tid & 127;
    int warp  = wgtid >> 5;
    int lane  = tid & 31;

    __shared__ __align__(16) bf16 Qs[2][64 * 32];
    __shared__ __align__(16) bf16 Ks[2][64 * 32];
    __shared__ __align__(16) bf16 Vs[2][64 * 32];

    uint32_t qb = smem_u32(&Qs[wg][0]);
    uint32_t kb = smem_u32(&Ks[wg][0]);
    uint32_t vb = smem_u32(&Vs[wg][0]);

    const bf16* src = qkv + (size_t)win * 49 * 576 + h * HDIM;
    for (int i = wgtid; i < 256; i += 128) {
        int row = i >> 2, c = i & 3;
        int sw = c ^ ((row >> 1) & 3);
        int sz = (row < 49) ? 16 : 0;
        const bf16* s = (row < 49) ? (src + (size_t)row * 576 + c * 8) : src;
        cp16z(qb + (row * 4 + sw) * 16, s, sz);
        cp16z(kb + (row * 4 + sw) * 16, s + CD, sz);
        cp16z(vb + (row * 4 + sw) * 16, s + 2 * CD, sz);
    }
    asm volatile("cp.async.commit_group;\n" ::: "memory");
    asm volatile("cp.async.wait_group 0;\n" ::: "memory");
    __syncthreads();

    float sacc[8][4];
    #pragma unroll
    for (int t = 0; t < 8; t++)
        #pragma unroll
        for (int i = 0; i < 4; i++) sacc[t][i] = 0.f;

    #pragma unroll
    for (int kk = 0; kk < 2; kk++) {
        uint32_t afr[4], bfr[4][4];
        {
            int r = warp * 16 + (lane & 15);
            int c = kk * 2 + (lane >> 4);
            int sw = c ^ ((r >> 1) & 3);
            ldsm_x4(afr, qb + (r * 4 + sw) * 16);
        }
        #pragma unroll
        for (int nb = 0; nb < 4; nb++) {
            int r = nb * 16 + ((lane >> 4) << 3) + (lane & 7);
            int c = kk * 2 + ((lane >> 3) & 1);
            int sw = c ^ ((r >> 1) & 3);
            ldsm_x4(bfr[nb], kb + (r * 4 + sw) * 16);
        }
        #pragma unroll
        for (int nt = 0; nt < 8; nt++)
            mma16816(sacc[nt], afr, &bfr[nt >> 1][(nt & 1) * 2]);
    }

    const float scale = 0.17677669529663687f;
    int gr = lane >> 2, gc2 = (lane & 3) * 2;
    int rbase = warp * 16 + gr;
    float mx[2] = {-1e30f, -1e30f}, sum[2] = {0.f, 0.f}, inv[2];

    #pragma unroll
    for (int half = 0; half < 2; half++) {
        int row = rbase + half * 8;
        int rc = (row < 49) ? row : 48;
        const float* bp = bias6 + ((size_t)h * 49 + rc) * 49;
        #pragma unroll
        for (int nt = 0; nt < 8; nt++) {
            #pragma unroll
            for (int j = 0; j < 2; j++) {
                int col = nt * 8 + gc2 + j;
                float v = sacc[nt][half * 2 + j] * scale;
                v = (col < 49 && row < 49) ? (v + bp[(col < 49) ? col : 48]) : -1e30f;
                sacc[nt][half * 2 + j] = v;
                mx[half] = fmaxf(mx[half], v);
            }
        }
        mx[half] = fmaxf(mx[half], __shfl_xor_sync(0xFFFFFFFFu, mx[half], 1));
        mx[half] = fmaxf(mx[half], __shfl_xor_sync(0xFFFFFFFFu, mx[half], 2));
        #pragma unroll
        for (int nt = 0; nt < 8; nt++) {
            #pragma unroll
            for (int j = 0; j < 2; j++) {
                float e = __expf(sacc[nt][half * 2 + j] - mx[half]);
                sacc[nt][half * 2 + j] = e;
                sum[half] += e;
            }
        }
        sum[half] += __shfl_xor_sync(0xFFFFFFFFu, sum[half], 1);
        sum[half] += __shfl_xor_sync(0xFFFFFFFFu, sum[half], 2);
        inv[half] = 1.f / sum[half];
    }

    uint32_t pfr[4][4];
    #pragma unroll
    for (int ks = 0; ks < 4; ks++) {
        int t0 = 2 * ks, t1 = t0 + 1;
        pfr[ks][0] = packbf(sacc[t0][0], sacc[t0][1]);
        pfr[ks][1] = packbf(sacc[t0][2], sacc[t0][3]);
        pfr[ks][2] = packbf(sacc[t1][0], sacc[t1][1]);
        pfr[ks][3] = packbf(sacc[t1][2], sacc[t1][3]);
    }

    float oacc[4][4];
    #pragma unroll
    for (int t = 0; t < 4; t++)
        #pragma unroll
        for (int i = 0; i < 4; i++) oacc[t][i] = 0.f;

    #pragma unroll
    for (int ks = 0; ks < 4; ks++) {
        uint32_t vfr[2][4];
        #pragma unroll
        for (int nb = 0; nb < 2; nb++) {
            int r = ks * 16 + ((lane >> 3) & 1) * 8 + (lane & 7);
            int c = nb * 2 + (lane >> 4);
            int sw = c ^ ((r >> 1) & 3);
            ldsm_x4t(vfr[nb], vb + (r * 4 + sw) * 16);
        }
        #pragma unroll
        for (int nt = 0; nt < 4; nt++)
            mma16816(oacc[nt], pfr[ks], &vfr[nt >> 1][(nt & 1) * 2]);
    }

    bf16* ob = out + (size_t)win * 49 * CD + h * HDIM;
    #pragma unroll
    for (int half = 0; half < 2; half++) {
        int row = rbase + half * 8;
        if (row < 49) {
            #pragma unroll
            for (int nt = 0; nt < 4; nt++) {
                int col = nt * 8 + gc2;
                __nv_bfloat162 o = __floats2bfloat162_rn(oacc[nt][half * 2] * inv[half],
                                                         oacc[nt][half * 2 + 1] * inv[half]);
                *(__nv_bfloat162*)(ob + (size_t)row * CD + col) = o;
            }
        }
    }
}

// ---------------- launch ----------------------------------------------------
extern "C" void kernel_launch(void* const* d_in, const int* in_sizes, int n_in,
                              void* d_out, int out_size)
{
    const float* x    = (const float*)d_in[0];
    const float* n1g  = (const float*)d_in[1];
    const float* n1b  = (const float*)d_in[2];
    const float* qkvw = (const float*)d_in[3];
    const float* qkvb = (const float*)d_in[4];
    const float* pw   = (const float*)d_in[5];
    const float* pb   = (const float*)d_in[6];
    const float* tab  = (const float*)d_in[7];
    const float* n2g  = (const float*)d_in[8];
    const float* n2b  = (const float*)d_in[9];
    const float* f1w  = (const float*)d_in[10];
    const float* f1b  = (const float*)d_in[11];
    const float* f2w  = (const float*)d_in[12];
    const float* f2b  = (const float*)d_in[13];
    const int*   ridx = (const int*)  d_in[14];

    bf16 *p_xwb, *p_qkvb, *p_attb, *p_xn2b, *p_hb, *p_wqkv, *p_wp, *p_wf1, *p_wf2;
    float *p_x2, *p_bias6;
    cudaGetSymbolAddress((void**)&p_xwb,  g_xwb);
    cudaGetSymbolAddress((void**)&p_qkvb, g_qkvb);
    cudaGetSymbolAddress((void**)&p_attb, g_attb);
    cudaGetSymbolAddress((void**)&p_x2,   g_x2);
    cudaGetSymbolAddress((void**)&p_xn2b, g_xn2b);
    cudaGetSymbolAddress((void**)&p_hb,   g_hb);
    cudaGetSymbolAddress((void**)&p_wqkv, g_wqkv);
    cudaGetSymbolAddress((void**)&p_wp,   g_wp);
    cudaGetSymbolAddress((void**)&p_wf1,  g_wf1);
    cudaGetSymbolAddress((void**)&p_wf2,  g_wf2);
    cudaGetSymbolAddress((void**)&p_bias6, g_bias6);

    cudaFuncSetAttribute(gemm_n192<0, bf16>,  cudaFuncAttributeMaxDynamicSharedMemorySize, GSM_TOT);
    cudaFuncSetAttribute(gemm_n192<1, bf16>,  cudaFuncAttributeMaxDynamicSharedMemorySize, GSM_TOT);
    cudaFuncSetAttribute(gemm_n192<2, float>, cudaFuncAttributeMaxDynamicSharedMemorySize, GSM_TOT);
    cudaFuncSetAttribute(gemm_n192<3, float>, cudaFuncAttributeMaxDynamicSharedMemorySize, GSM_TOT);

    // 0. weights -> bf16, bias table -> dense
    prep_kernel<<<(N_WTOT + N_BIAS + 255) / 256, 256>>>(qkvw, pw, f1w, f2w, tab, ridx);
    // 1. LN1 + shift + window partition
    ln_warp<<<TOK / 8, 256>>>(x, n1g, n1b, p_xwb);
    // 2. QKV GEMM -> bf16
    gemm_n192<0, bf16><<<dim3(576 / GBN, TOK / GBM), NTH, GSM_TOT>>>(
        p_xwb, p_wqkv, qkvb, nullptr, p_qkvb, 576, CD, nullptr, nullptr, nullptr);
    // 3. attention (tensor cores)
    attn_mma<<<dim3(3, NWIN), 256>>>(p_qkvb, p_bias6, p_attb);
    // 4. proj GEMM + reverse/unshift scatter + residual(x) -> x2, fused LN2 -> xn2
    gemm_n192<3, float><<<dim3(1, TOK / GBM), NTH, GSM_TOT>>>(
        p_attb, p_wp, pb, x, p_x2, CD, CD, n2g, n2b, p_xn2b);
    // 5. FC1 + GELU
    gemm_n192<1, bf16><<<dim3(HID / GBN, TOK / GBM), NTH, GSM_TOT>>>(
        p_xn2b, p_wf1, f1b, nullptr, p_hb, HID, CD, nullptr, nullptr, nullptr);
    // 6. FC2 + residual(x2) -> d_out
    gemm_n192<2, float><<<dim3(1, TOK / GBM), NTH, GSM_TOT>>>(
        p_hb, p_wf2, f2b, p_x2, (float*)d_out, CD, HID, nullptr, nullptr, nullptr);
}

// round 13
// speedup vs baseline: 1.1029x; 1.1029x over previous
#include <cuda_runtime.h>
#include <cuda_bf16.h>
#include <math.h>
#include <stdint.h>

#define TOK   100352
#define CD    192
#define NWIN  2048
#define NHEAD 6
#define HDIM  32
#define HID   768

typedef __nv_bfloat16 bf16;

// ---------------- scratch ----------------------------------------------------
__device__ bf16  g_xwb [(size_t)TOK * CD];
__device__ bf16  g_qkvb[(size_t)TOK * 3 * CD];
__device__ bf16  g_attb[(size_t)TOK * CD];
__device__ float g_x2  [(size_t)TOK * CD];
__device__ bf16  g_xn2b[(size_t)TOK * CD];
__device__ bf16  g_hb  [(size_t)TOK * HID];
__device__ bf16  g_wqkv[576 * CD];
__device__ bf16  g_wp  [CD * CD];
__device__ bf16  g_wf1 [HID * CD];
__device__ bf16  g_wf2 [CD * HID];
__device__ float g_bias6[NHEAD * 49 * 49];

#define N_QKVW (576 * CD)
#define N_PW   (CD * CD)
#define N_F1W  (HID * CD)
#define N_F2W  (CD * HID)
#define N_WTOT (N_QKVW + N_PW + N_F1W + N_F2W)
#define N_BIAS (NHEAD * 49 * 49)
#define LN1_BLOCKS (TOK / 8)
#define PREP_BLOCKS ((N_WTOT + N_BIAS + 255) / 256)

// ---------------- fused LN1(+shift+gather) AND weight prep ------------------
__global__ __launch_bounds__(256)
void ln1_prep_kernel(const float* __restrict__ xin,
                     const float* __restrict__ gamma,
                     const float* __restrict__ beta,
                     bf16* __restrict__ out,
                     const float* __restrict__ qkvw, const float* __restrict__ pw,
                     const float* __restrict__ f1w, const float* __restrict__ f2w,
                     const float* __restrict__ tab, const int* __restrict__ ridx)
{
    if (blockIdx.x >= LN1_BLOCKS) {
        int i = (blockIdx.x - LN1_BLOCKS) * 256 + threadIdx.x;
        if (i < N_QKVW) { g_wqkv[i] = __float2bfloat16(qkvw[i]); return; }
        i -= N_QKVW;
        if (i < N_PW)   { g_wp[i]   = __float2bfloat16(pw[i]);   return; }
        i -= N_PW;
        if (i < N_F1W)  { g_wf1[i]  = __float2bfloat16(f1w[i]);  return; }
        i -= N_F1W;
        if (i < N_F2W)  { g_wf2[i]  = __float2bfloat16(f2w[i]);  return; }
        i -= N_F2W;
        if (i < N_BIAS) {
            int h = i / 2401, nm = i - h * 2401;
            g_bias6[i] = tab[ridx[nm] * NHEAD + h];
        }
        return;
    }
    int m = blockIdx.x * 8 + (threadIdx.x >> 5);
    int lane = threadIdx.x & 31;
    int w = m / 49, n = m - w * 49;
    int bb = w >> 6, rem = w & 63, hb = rem >> 3, wb = rem & 7;
    int r = n / 7, cn = n - r * 7;
    int hh = hb * 7 + r + 3;  if (hh >= 56) hh -= 56;
    int ww = wb * 7 + cn + 3; if (ww >= 56) ww -= 56;
    size_t src = ((size_t)bb * 3136 + hh * 56 + ww);

    const float* p = xin + src * CD;
    float v[6];
    float s = 0.f, s2 = 0.f;
    #pragma unroll
    for (int i = 0; i < 6; i++) {
        v[i] = p[lane + 32 * i];
        s += v[i]; s2 += v[i] * v[i];
    }
    #pragma unroll
    for (int o = 16; o > 0; o >>= 1) {
        s  += __shfl_xor_sync(0xFFFFFFFFu, s,  o);
        s2 += __shfl_xor_sync(0xFFFFFFFFu, s2, o);
    }
    float mean = s * (1.f / CD);
    float var  = s2 * (1.f / CD) - mean * mean;
    float inv  = rsqrtf(var + 1e-5f);
    bf16* o = out + (size_t)m * CD;
    #pragma unroll
    for (int i = 0; i < 6; i++) {
        int c = lane + 32 * i;
        o[c] = __float2bfloat16((v[i] - mean) * inv * gamma[c] + beta[c]);
    }
}

// ---------------- LayerNorm (plain, for LN2): one warp per token ------------
__global__ __launch_bounds__(256)
void ln_warp2(const float* __restrict__ xin,
              const float* __restrict__ gamma,
              const float* __restrict__ beta,
              bf16* __restrict__ out)
{
    int m = blockIdx.x * 8 + (threadIdx.x >> 5);
    int lane = threadIdx.x & 31;
    const float* p = xin + (size_t)m * CD;
    float v[6];
    float s = 0.f, s2 = 0.f;
    #pragma unroll
    for (int i = 0; i < 6; i++) {
        v[i] = p[lane + 32 * i];
        s += v[i]; s2 += v[i] * v[i];
    }
    #pragma unroll
    for (int o = 16; o > 0; o >>= 1) {
        s  += __shfl_xor_sync(0xFFFFFFFFu, s,  o);
        s2 += __shfl_xor_sync(0xFFFFFFFFu, s2, o);
    }
    float mean = s * (1.f / CD);
    float var  = s2 * (1.f / CD) - mean * mean;
    float inv  = rsqrtf(var + 1e-5f);
    bf16* o = out + (size_t)m * CD;
    #pragma unroll
    for (int i = 0; i < 6; i++) {
        int c = lane + 32 * i;
        o[c] = __float2bfloat16((v[i] - mean) * inv * gamma[c] + beta[c]);
    }
}

// ---------------- helpers ----------------------------------------------------
__device__ __forceinline__ void cp16(uint32_t dst, const void* src) {
    asm volatile("cp.async.cg.shared.global [%0], [%1], 16;\n" :: "r"(dst), "l"(src));
}
__device__ __forceinline__ void cp16z(uint32_t dst, const void* src, int sz) {
    asm volatile("cp.async.cg.shared.global [%0], [%1], 16, %2;\n" :: "r"(dst), "l"(src), "r"(sz));
}
__device__ __forceinline__ void ldsm_x4(uint32_t* r, uint32_t addr) {
    asm volatile("ldmatrix.sync.aligned.m8n8.x4.shared.b16 {%0,%1,%2,%3}, [%4];\n"
                 : "=r"(r[0]), "=r"(r[1]), "=r"(r[2]), "=r"(r[3]) : "r"(addr));
}
__device__ __forceinline__ void ldsm_x4t(uint32_t* r, uint32_t addr) {
    asm volatile("ldmatrix.sync.aligned.m8n8.x4.trans.shared.b16 {%0,%1,%2,%3}, [%4];\n"
                 : "=r"(r[0]), "=r"(r[1]), "=r"(r[2]), "=r"(r[3]) : "r"(addr));
}
__device__ __forceinline__ void mma16816(float* d, const uint32_t* a, const uint32_t* b) {
    asm volatile(
        "mma.sync.aligned.m16n8k16.row.col.f32.bf16.bf16.f32 "
        "{%0,%1,%2,%3}, {%4,%5,%6,%7}, {%8,%9}, {%0,%1,%2,%3};\n"
        : "+f"(d[0]), "+f"(d[1]), "+f"(d[2]), "+f"(d[3])
        : "r"(a[0]), "r"(a[1]), "r"(a[2]), "r"(a[3]), "r"(b[0]), "r"(b[1]));
}
__device__ __forceinline__ uint32_t packbf(float a, float b) {
    __nv_bfloat162 t = __floats2bfloat162_rn(a, b);
    return *(uint32_t*)&t;
}
__device__ __forceinline__ uint32_t smem_u32(const void* p) {
    return (uint32_t)__cvta_generic_to_shared(p);
}

// ---------------- bf16 GEMM: C[M,N] = A[M,K] @ B[N,K]^T + bias --------------
// Block tile 256(M) x 64(N), BK=32, 3-stage cp.async, SINGLE barrier/iter:
//   wait_group -> __syncthreads -> stage((it+2)%3) -> compute(it%3)
// (staging after the barrier means all warps finished compute(it-1), which is
//  the last reader of buffer (it+2)%3 == (it-1)%3 -> race-free.)
// 8 warps along M; warp tile 32(M) x 64(N); mma.m16n8k16.
// MODE 0: bf16 out (qkv) | 1: GELU bf16 (fc1) | 2: +aux fp32 (fc2 -> d_out)
// MODE 3: proj: scatter (window-reverse + unshift) + residual -> x2 (fp32)
#define GBM 256
#define GBN 64
#define GBK 32
#define SA_STG 16384           // 256 rows * 64B
#define SB_STG 4096            // 64 rows * 64B
#define OFF_A(s) ((s) * SA_STG)
#define OFF_B(s) (3 * SA_STG + (s) * SB_STG)
#define GSM_TOT  (3 * SA_STG + 3 * SB_STG)     // 61440

template <int MODE, typename OutT>
__global__ __launch_bounds__(256, 2)
void gemm_m256(const bf16* __restrict__ A, const bf16* __restrict__ B,
               const float* __restrict__ bias, const float* __restrict__ aux,
               OutT* __restrict__ Cout, int N, int K)
{
    extern __shared__ __align__(128) char smem[];
    uint32_t sb = smem_u32(smem);

    int tid = threadIdx.x;
    int warp = tid >> 5, lane = tid & 31;
    int row0 = blockIdx.y * GBM;
    int col0 = blockIdx.x * GBN;

    float acc[2][8][4];
    #pragma unroll
    for (int mt = 0; mt < 2; mt++)
        #pragma unroll
        for (int nt = 0; nt < 8; nt++)
            #pragma unroll
            for (int i = 0; i < 4; i++) acc[mt][nt][i] = 0.f;

    const int nk = K / GBK;

    auto stage = [&](int s, int k0) {
        #pragma unroll
        for (int j = 0; j < 4; j++) {                   // A: 1024 x 16B
            int idx = tid + j * 256;
            int r = idx >> 2, c = idx & 3;
            int sw = c ^ ((r >> 1) & 3);
            cp16(sb + OFF_A(s) + (r * 4 + sw) * 16,
                 A + (size_t)(row0 + r) * K + k0 + c * 8);
        }
        {                                               // B: 256 x 16B
            int r = tid >> 2, c = tid & 3;
            int sw = c ^ ((r >> 1) & 3);
            cp16(sb + OFF_B(s) + (r * 4 + sw) * 16,
                 B + (size_t)(col0 + r) * K + k0 + c * 8);
        }
        asm volatile("cp.async.commit_group;\n" ::: "memory");
    };

    stage(0, 0);
    stage(1, GBK);

    for (int it = 0; it < nk; it++) {
        if (it + 1 < nk) asm volatile("cp.async.wait_group 1;\n" ::: "memory");
        else             asm volatile("cp.async.wait_group 0;\n" ::: "memory");
        __syncthreads();
        if (it + 2 < nk) stage((it + 2) % 3, (it + 2) * GBK);

        int s = it % 3;
        uint32_t aB = sb + OFF_A(s);
        uint32_t bB = sb + OFF_B(s);
        #pragma unroll
        for (int kk = 0; kk < 2; kk++) {
            uint32_t afr[2][4], bfr[4][4];
            #pragma unroll
            for (int mt = 0; mt < 2; mt++) {
                int r = warp * 32 + mt * 16 + (lane & 15);
                int c = kk * 2 + (lane >> 4);
                int sw = c ^ ((r >> 1) & 3);
                ldsm_x4(afr[mt], aB + (r * 4 + sw) * 16);
            }
            #pragma unroll
            for (int nb = 0; nb < 4; nb++) {
                int r = nb * 16 + ((lane >> 4) << 3) + (lane & 7);
                int c = kk * 2 + ((lane >> 3) & 1);
                int sw = c ^ ((r >> 1) & 3);
                ldsm_x4(bfr[nb], bB + (r * 4 + sw) * 16);
            }
            #pragma unroll
            for (int mt = 0; mt < 2; mt++)
                #pragma unroll
                for (int nt = 0; nt < 8; nt++)
                    mma16816(acc[mt][nt], afr[mt], &bfr[nt >> 1][(nt & 1) * 2]);
        }
    }

    // ---- epilogue ----
    int gr = lane >> 2, gc = lane & 3;
    #pragma unroll
    for (int mt = 0; mt < 2; mt++) {
        #pragma unroll
        for (int half = 0; half < 2; half++) {
            int row = row0 + warp * 32 + mt * 16 + gr + half * 8;
            size_t orow = row;
            if (MODE == 3) {
                int w = row / 49, n = row - w * 49;
                int bb = w >> 6, rem = w & 63, hb = rem >> 3, wb = rem & 7;
                int r = n / 7, cn = n - r * 7;
                int hh = hb * 7 + r + 3;  if (hh >= 56) hh -= 56;
                int ww = wb * 7 + cn + 3; if (ww >= 56) ww -= 56;
                orow = ((size_t)bb * 3136 + hh * 56 + ww);
            }
            #pragma unroll
            for (int nt = 0; nt < 8; nt++) {
                int col = col0 + nt * 8 + gc * 2;
                float v0 = acc[mt][nt][half * 2 + 0] + bias[col];
                float v1 = acc[mt][nt][half * 2 + 1] + bias[col + 1];
                if (MODE == 1) {
                    v0 = 0.5f * v0 * (1.f + erff(v0 * 0.70710678118654752f));
                    v1 = 0.5f * v1 * (1.f + erff(v1 * 0.70710678118654752f));
                } else if (MODE == 2) {
                    const float* ap = aux + (size_t)row * N + col;
                    v0 += ap[0]; v1 += ap[1];
                } else if (MODE == 3) {
                    const float* ap = aux + orow * CD + col;
                    v0 += ap[0]; v1 += ap[1];
                }
                if (sizeof(OutT) == 2) {
                    *(uint32_t*)((bf16*)Cout + (size_t)row * N + col) = packbf(v0, v1);
                } else if (MODE == 3) {
                    *(float2*)((float*)Cout + orow * CD + col) = make_float2(v0, v1);
                } else {
                    *(float2*)((float*)Cout + (size_t)row * N + col) = make_float2(v0, v1);
                }
            }
        }
    }
}

// ---------------- MMA attention: block = (window, head pair) ----------------
__global__ __launch_bounds__(256)
void attn_mma(const bf16* __restrict__ qkv,
              const float* __restrict__ bias6,
              bf16* __restrict__ out)
{
    int win = blockIdx.y;
    int hp  = blockIdx.x;
    int tid = threadIdx.x;
    int wg  = tid >> 7;
    int h   = hp * 2 + wg;
    int wgtid = tid & 127;
    int warp  = wgtid >> 5;
    int lane  = tid & 31;

    __shared__ __align__(16) bf16 Qs[2][64 * 32];
    __shared__ __align__(16) bf16 Ks[2][64 * 32];
    __shared__ __align__(16) bf16 Vs[2][64 * 32];

    uint32_t qb = smem_u32(&Qs[wg][0]);
    uint32_t kb = smem_u32(&Ks[wg][0]);
    uint32_t vb = smem_u32(&Vs[wg][0]);

    const bf16* src = qkv + (size_t)win * 49 * 576 + h * HDIM;
    for (int i = wgtid; i < 256; i += 128) {
        int row = i >> 2, c = i & 3;
        int sw = c ^ ((row >> 1) & 3);
        int sz = (row < 49) ? 16 : 0;
        const bf16* s = (row < 49) ? (src + (size_t)row * 576 + c * 8) : src;
        cp16z(qb + (row * 4 + sw) * 16, s, sz);
        cp16z(kb + (row * 4 + sw) * 16, s + CD, sz);
        cp16z(vb + (row * 4 + sw) * 16, s + 2 * CD, sz);
    }
    asm volatile("cp.async.commit_group;\n" ::: "memory");
    asm volatile("cp.async.wait_group 0;\n" ::: "memory");
    __syncthreads();

    float sacc[8][4];
    #pragma unroll
    for (int t = 0; t < 8; t++)
        #pragma unroll
        for (int i = 0; i < 4; i++) sacc[t][i] = 0.f;

    #pragma unroll
    for (int kk = 0; kk < 2; kk++) {
        uint32_t afr[4], bfr[4][4];
        {
            int r = warp * 16 + (lane & 15);
            int c = kk * 2 + (lane >> 4);
            int sw = c ^ ((r >> 1) & 3);
            ldsm_x4(afr, qb + (r * 4 + sw) * 16);
        }
        #pragma unroll
        for (int nb = 0; nb < 4; nb++) {
            int r = nb * 16 + ((lane >> 4) << 3) + (lane & 7);
            int c = kk * 2 + ((lane >> 3) & 1);
            int sw = c ^ ((r >> 1) & 3);
            ldsm_x4(bfr[nb], kb + (r * 4 + sw) * 16);
        }
        #pragma unroll
        for (int nt = 0; nt < 8; nt++)
            mma16816(sacc[nt], afr, &bfr[nt >> 1][(nt & 1) * 2]);
    }

    const float scale = 0.17677669529663687f;
    int gr = lane >> 2, gc2 = (lane & 3) * 2;
    int rbase = warp * 16 + gr;
    float mx[2] = {-1e30f, -1e30f}, sum[2] = {0.f, 0.f}, inv[2];

    #pragma unroll
    for (int half = 0; half < 2; half++) {
        int row = rbase + half * 8;
        int rc = (row < 49) ? row : 48;
        const float* bp = bias6 + ((size_t)h * 49 + rc) * 49;
        #pragma unroll
        for (int nt = 0; nt < 8; nt++) {
            #pragma unroll
            for (int j = 0; j < 2; j++) {
                int col = nt * 8 + gc2 + j;
                float v = sacc[nt][half * 2 + j] * scale;
                v = (col < 49 && row < 49) ? (v + bp[(col < 49) ? col : 48]) : -1e30f;
                sacc[nt][half * 2 + j] = v;
                mx[half] = fmaxf(mx[half], v);
            }
        }
        mx[half] = fmaxf(mx[half], __shfl_xor_sync(0xFFFFFFFFu, mx[half], 1));
        mx[half] = fmaxf(mx[half], __shfl_xor_sync(0xFFFFFFFFu, mx[half], 2));
        #pragma unroll
        for (int nt = 0; nt < 8; nt++) {
            #pragma unroll
            for (int j = 0; j < 2; j++) {
                float e = __expf(sacc[nt][half * 2 + j] - mx[half]);
                sacc[nt][half * 2 + j] = e;
                sum[half] += e;
            }
        }
        sum[half] += __shfl_xor_sync(0xFFFFFFFFu, sum[half], 1);
        sum[half] += __shfl_xor_sync(0xFFFFFFFFu, sum[half], 2);
        inv[half] = 1.f / sum[half];
    }

    uint32_t pfr[4][4];
    #pragma unroll
    for (int ks = 0; ks < 4; ks++) {
        int t0 = 2 * ks, t1 = t0 + 1;
        pfr[ks][0] = packbf(sacc[t0][0], sacc[t0][1]);
        pfr[ks][1] = packbf(sacc[t0][2], sacc[t0][3]);
        pfr[ks][2] = packbf(sacc[t1][0], sacc[t1][1]);
        pfr[ks][3] = packbf(sacc[t1][2], sacc[t1][3]);
    }

    float oacc[4][4];
    #pragma unroll
    for (int t = 0; t < 4; t++)
        #pragma unroll
        for (int i = 0; i < 4; i++) oacc[t][i] = 0.f;

    #pragma unroll
    for (int ks = 0; ks < 4; ks++) {
        uint32_t vfr[2][4];
        #pragma unroll
        for (int nb = 0; nb < 2; nb++) {
            int r = ks * 16 + ((lane >> 3) & 1) * 8 + (lane & 7);
            int c = nb * 2 + (lane >> 4);
            int sw = c ^ ((r >> 1) & 3);
            ldsm_x4t(vfr[nb], vb + (r * 4 + sw) * 16);
        }
        #pragma unroll
        for (int nt = 0; nt < 4; nt++)
            mma16816(oacc[nt], pfr[ks], &vfr[nt >> 1][(nt & 1) * 2]);
    }

    bf16* ob = out + (size_t)win * 49 * CD + h * HDIM;
    #pragma unroll
    for (int half = 0; half < 2; half++) {
        int row = rbase + half * 8;
        if (row < 49) {
            #pragma unroll
            for (int nt = 0; nt < 4; nt++) {
                int col = nt * 8 + gc2;
                __nv_bfloat162 o = __floats2bfloat162_rn(oacc[nt][half * 2] * inv[half],
                                                         oacc[nt][half * 2 + 1] * inv[half]);
                *(__nv_bfloat162*)(ob + (size_t)row * CD + col) = o;
            }
        }
    }
}

// ---------------- launch ----------------------------------------------------
extern "C" void kernel_launch(void* const* d_in, const int* in_sizes, int n_in,
                              void* d_out, int out_size)
{
    const float* x    = (const float*)d_in[0];
    const float* n1g  = (const float*)d_in[1];
    const float* n1b  = (const float*)d_in[2];
    const float* qkvw = (const float*)d_in[3];
    const float* qkvb = (const float*)d_in[4];
    const float* pw   = (const float*)d_in[5];
    const float* pb   = (const float*)d_in[6];
    const float* tab  = (const float*)d_in[7];
    const float* n2g  = (const float*)d_in[8];
    const float* n2b  = (const float*)d_in[9];
    const float* f1w  = (const float*)d_in[10];
    const float* f1b  = (const float*)d_in[11];
    const float* f2w  = (const float*)d_in[12];
    const float* f2b  = (const float*)d_in[13];
    const int*   ridx = (const int*)  d_in[14];

    bf16 *p_xwb, *p_qkvb, *p_attb, *p_xn2b, *p_hb;
    float *p_x2, *p_bias6;
    bf16 *p_wqkv, *p_wp, *p_wf1, *p_wf2;
    cudaGetSymbolAddress((void**)&p_xwb,  g_xwb);
    cudaGetSymbolAddress((void**)&p_qkvb, g_qkvb);
    cudaGetSymbolAddress((void**)&p_attb, g_attb);
    cudaGetSymbolAddress((void**)&p_x2,   g_x2);
    cudaGetSymbolAddress((void**)&p_xn2b, g_xn2b);
    cudaGetSymbolAddress((void**)&p_hb,   g_hb);
    cudaGetSymbolAddress((void**)&p_wqkv, g_wqkv);
    cudaGetSymbolAddress((void**)&p_wp,   g_wp);
    cudaGetSymbolAddress((void**)&p_wf1,  g_wf1);
    cudaGetSymbolAddress((void**)&p_wf2,  g_wf2);
    cudaGetSymbolAddress((void**)&p_bias6, g_bias6);

    cudaFuncSetAttribute(gemm_m256<0, bf16>,  cudaFuncAttributeMaxDynamicSharedMemorySize, GSM_TOT);
    cudaFuncSetAttribute(gemm_m256<1, bf16>,  cudaFuncAttributeMaxDynamicSharedMemorySize, GSM_TOT);
    cudaFuncSetAttribute(gemm_m256<2, float>, cudaFuncAttributeMaxDynamicSharedMemorySize, GSM_TOT);
    cudaFuncSetAttribute(gemm_m256<3, float>, cudaFuncAttributeMaxDynamicSharedMemorySize, GSM_TOT);

    // 1. LN1 + shift + window partition, fused with weight prep
    ln1_prep_kernel<<<LN1_BLOCKS + PREP_BLOCKS, 256>>>(
        x, n1g, n1b, p_xwb, qkvw, pw, f1w, f2w, tab, ridx);
    // 2. QKV GEMM -> bf16
    gemm_m256<0, bf16><<<dim3(576 / GBN, TOK / GBM), 256, GSM_TOT>>>(
        p_xwb, p_wqkv, qkvb, nullptr, p_qkvb, 576, CD);
    // 3. attention (tensor cores)
    attn_mma<<<dim3(3, NWIN), 256>>>(p_qkvb, p_bias6, p_attb);
    // 4. proj GEMM + reverse/unshift scatter + residual(x) -> x2
    gemm_m256<3, float><<<dim3(CD / GBN, TOK / GBM), 256, GSM_TOT>>>(
        p_attb, p_wp, pb, x, p_x2, CD, CD);
    // 5. LN2
    ln_warp2<<<TOK / 8, 256>>>(p_x2, n2g, n2b, p_xn2b);
    // 6. FC1 + GELU
    gemm_m256<1, bf16><<<dim3(HID / GBN, TOK / GBM), 256, GSM_TOT>>>(
        p_xn2b, p_wf1, f1b, nullptr, p_hb, HID, CD);
    // 7. FC2 + residual(x2) -> d_out
    gemm_m256<2, float><<<dim3(CD / GBN, TOK / GBM), 256, GSM_TOT>>>(
        p_hb, p_wf2, f2b, p_x2, (float*)d_out, CD, HID);
}

// round 14
// speedup vs baseline: 1.1670x; 1.0581x over previous
#include <cuda_runtime.h>
#include <cuda_bf16.h>
#include <math.h>
#include <stdint.h>

#define TOK   100352
#define CD    192
#define NWIN  2048
#define NHEAD 6
#define HDIM  32
#define HID   768

typedef __nv_bfloat16 bf16;

// ---------------- scratch ----------------------------------------------------
__device__ bf16  g_xwb [(size_t)TOK * CD];
__device__ bf16  g_qkvb[(size_t)TOK * 3 * CD];
__device__ bf16  g_attb[(size_t)TOK * CD];
__device__ float g_x2  [(size_t)TOK * CD];
__device__ bf16  g_xn2b[(size_t)TOK * CD];
__device__ bf16  g_hb  [(size_t)TOK * HID];
__device__ bf16  g_wqkv[576 * CD];
__device__ bf16  g_wp  [CD * CD];
__device__ bf16  g_wf1 [HID * CD];
__device__ bf16  g_wf2 [CD * HID];
__device__ float g_bias6[NHEAD * 49 * 49];

#define N_QKVW (576 * CD)
#define N_PW   (CD * CD)
#define N_F1W  (HID * CD)
#define N_F2W  (CD * HID)
#define N_WTOT (N_QKVW + N_PW + N_F1W + N_F2W)
#define N_BIAS (NHEAD * 49 * 49)
#define LN1_BLOCKS (TOK / 8)
#define PREP_BLOCKS ((N_WTOT + N_BIAS + 255) / 256)

// ---------------- fused LN1(+shift+gather) AND weight prep ------------------
__global__ __launch_bounds__(256)
void ln1_prep_kernel(const float* __restrict__ xin,
                     const float* __restrict__ gamma,
                     const float* __restrict__ beta,
                     bf16* __restrict__ out,
                     const float* __restrict__ qkvw, const float* __restrict__ pw,
                     const float* __restrict__ f1w, const float* __restrict__ f2w,
                     const float* __restrict__ tab, const int* __restrict__ ridx)
{
    if (blockIdx.x >= LN1_BLOCKS) {
        int i = (blockIdx.x - LN1_BLOCKS) * 256 + threadIdx.x;
        if (i < N_QKVW) { g_wqkv[i] = __float2bfloat16(qkvw[i]); return; }
        i -= N_QKVW;
        if (i < N_PW)   { g_wp[i]   = __float2bfloat16(pw[i]);   return; }
        i -= N_PW;
        if (i < N_F1W)  { g_wf1[i]  = __float2bfloat16(f1w[i]);  return; }
        i -= N_F1W;
        if (i < N_F2W)  { g_wf2[i]  = __float2bfloat16(f2w[i]);  return; }
        i -= N_F2W;
        if (i < N_BIAS) {
            int h = i / 2401, nm = i - h * 2401;
            g_bias6[i] = tab[ridx[nm] * NHEAD + h];
        }
        return;
    }
    int m = blockIdx.x * 8 + (threadIdx.x >> 5);
    int lane = threadIdx.x & 31;
    int w = m / 49, n = m - w * 49;
    int bb = w >> 6, rem = w & 63, hb = rem >> 3, wb = rem & 7;
    int r = n / 7, cn = n - r * 7;
    int hh = hb * 7 + r + 3;  if (hh >= 56) hh -= 56;
    int ww = wb * 7 + cn + 3; if (ww >= 56) ww -= 56;
    size_t src = ((size_t)bb * 3136 + hh * 56 + ww);

    const float* p = xin + src * CD;
    float v[6];
    float s = 0.f, s2 = 0.f;
    #pragma unroll
    for (int i = 0; i < 6; i++) {
        v[i] = p[lane + 32 * i];
        s += v[i]; s2 += v[i] * v[i];
    }
    #pragma unroll
    for (int o = 16; o > 0; o >>= 1) {
        s  += __shfl_xor_sync(0xFFFFFFFFu, s,  o);
        s2 += __shfl_xor_sync(0xFFFFFFFFu, s2, o);
    }
    float mean = s * (1.f / CD);
    float var  = s2 * (1.f / CD) - mean * mean;
    float inv  = rsqrtf(var + 1e-5f);
    bf16* o = out + (size_t)m * CD;
    #pragma unroll
    for (int i = 0; i < 6; i++) {
        int c = lane + 32 * i;
        o[c] = __float2bfloat16((v[i] - mean) * inv * gamma[c] + beta[c]);
    }
}

// ---------------- LayerNorm (plain, for LN2): one warp per token ------------
__global__ __launch_bounds__(256)
void ln_warp2(const float* __restrict__ xin,
              const float* __restrict__ gamma,
              const float* __restrict__ beta,
              bf16* __restrict__ out)
{
    int m = blockIdx.x * 8 + (threadIdx.x >> 5);
    int lane = threadIdx.x & 31;
    const float* p = xin + (size_t)m * CD;
    float v[6];
    float s = 0.f, s2 = 0.f;
    #pragma unroll
    for (int i = 0; i < 6; i++) {
        v[i] = p[lane + 32 * i];
        s += v[i]; s2 += v[i] * v[i];
    }
    #pragma unroll
    for (int o = 16; o > 0; o >>= 1) {
        s  += __shfl_xor_sync(0xFFFFFFFFu, s,  o);
        s2 += __shfl_xor_sync(0xFFFFFFFFu, s2, o);
    }
    float mean = s * (1.f / CD);
    float var  = s2 * (1.f / CD) - mean * mean;
    float inv  = rsqrtf(var + 1e-5f);
    bf16* o = out + (size_t)m * CD;
    #pragma unroll
    for (int i = 0; i < 6; i++) {
        int c = lane + 32 * i;
        o[c] = __float2bfloat16((v[i] - mean) * inv * gamma[c] + beta[c]);
    }
}

// ---------------- helpers ----------------------------------------------------
__device__ __forceinline__ void cp16(uint32_t dst, const void* src) {
    asm volatile("cp.async.cg.shared.global [%0], [%1], 16;\n" :: "r"(dst), "l"(src));
}
__device__ __forceinline__ void cp16z(uint32_t dst, const void* src, int sz) {
    asm volatile("cp.async.cg.shared.global [%0], [%1], 16, %2;\n" :: "r"(dst), "l"(src), "r"(sz));
}
__device__ __forceinline__ void ldsm_x4(uint32_t* r, uint32_t addr) {
    asm volatile("ldmatrix.sync.aligned.m8n8.x4.shared.b16 {%0,%1,%2,%3}, [%4];\n"
                 : "=r"(r[0]), "=r"(r[1]), "=r"(r[2]), "=r"(r[3]) : "r"(addr));
}
__device__ __forceinline__ void ldsm_x4t(uint32_t* r, uint32_t addr) {
    asm volatile("ldmatrix.sync.aligned.m8n8.x4.trans.shared.b16 {%0,%1,%2,%3}, [%4];\n"
                 : "=r"(r[0]), "=r"(r[1]), "=r"(r[2]), "=r"(r[3]) : "r"(addr));
}
__device__ __forceinline__ void mma16816(float* d, const uint32_t* a, const uint32_t* b) {
    asm volatile(
        "mma.sync.aligned.m16n8k16.row.col.f32.bf16.bf16.f32 "
        "{%0,%1,%2,%3}, {%4,%5,%6,%7}, {%8,%9}, {%0,%1,%2,%3};\n"
        : "+f"(d[0]), "+f"(d[1]), "+f"(d[2]), "+f"(d[3])
        : "r"(a[0]), "r"(a[1]), "r"(a[2]), "r"(a[3]), "r"(b[0]), "r"(b[1]));
}
__device__ __forceinline__ uint32_t packbf(float a, float b) {
    __nv_bfloat162 t = __floats2bfloat162_rn(a, b);
    return *(uint32_t*)&t;
}
__device__ __forceinline__ uint32_t smem_u32(const void* p) {
    return (uint32_t)__cvta_generic_to_shared(p);
}

// ---------------- bf16 GEMM: C[M,N] = A[M,K] @ B[N,K]^T + bias --------------
// Block tile 128(M) x 64(N), BK=64, 2-stage double buffer, 128 threads.
// 4 warps along M; warp tile 32(M) x 64(N); mma.m16n8k16, 4 kk sub-iters.
// Rows are 128B (full SW128 swizzle: chunk c ^ (r&7)).
// Small CTA -> 4 independent CTAs/SM (RF 128 regs/thread cap) for latency hiding.
// MODE 0: bf16 out (qkv) | 1: GELU bf16 (fc1) | 2: +aux fp32 (fc2 -> d_out)
// MODE 3: proj: scatter (window-reverse + unshift) + residual -> x2 (fp32)
#define GBM 128
#define GBN 64
#define GBK 64
#define NTH 128
#define SA_STG 16384           // 128 rows * 128B
#define SB_STG 8192            // 64 rows * 128B
#define OFF_A(s) ((s) * SA_STG)
#define OFF_B(s) (2 * SA_STG + (s) * SB_STG)
#define GSM_TOT  (2 * SA_STG + 2 * SB_STG)     // 49152

template <int MODE, typename OutT>
__global__ __launch_bounds__(NTH, 4)
void gemm_s128(const bf16* __restrict__ A, const bf16* __restrict__ B,
               const float* __restrict__ bias, const float* __restrict__ aux,
               OutT* __restrict__ Cout, int N, int K)
{
    extern __shared__ __align__(128) char smem[];
    uint32_t sb = smem_u32(smem);

    int tid = threadIdx.x;
    int warp = tid >> 5, lane = tid & 31;
    int row0 = blockIdx.y * GBM;
    int col0 = blockIdx.x * GBN;

    float acc[2][8][4];
    #pragma unroll
    for (int mt = 0; mt < 2; mt++)
        #pragma unroll
        for (int nt = 0; nt < 8; nt++)
            #pragma unroll
            for (int i = 0; i < 4; i++) acc[mt][nt][i] = 0.f;

    const int nk = K / GBK;

    auto stage = [&](int s, int k0) {
        #pragma unroll
        for (int j = 0; j < 8; j++) {                   // A: 1024 x 16B
            int idx = tid + j * NTH;
            int r = idx >> 3, c = idx & 7;
            int sw = c ^ (r & 7);
            cp16(sb + OFF_A(s) + r * 128 + sw * 16,
                 A + (size_t)(row0 + r) * K + k0 + c * 8);
        }
        #pragma unroll
        for (int j = 0; j < 4; j++) {                   // B: 512 x 16B
            int idx = tid + j * NTH;
            int r = idx >> 3, c = idx & 7;
            int sw = c ^ (r & 7);
            cp16(sb + OFF_B(s) + r * 128 + sw * 16,
                 B + (size_t)(col0 + r) * K + k0 + c * 8);
        }
        asm volatile("cp.async.commit_group;\n" ::: "memory");
    };

    stage(0, 0);

    for (int it = 0; it < nk; it++) {
        if (it + 1 < nk) {
            stage((it + 1) & 1, (it + 1) * GBK);
            asm volatile("cp.async.wait_group 1;\n" ::: "memory");
        } else {
            asm volatile("cp.async.wait_group 0;\n" ::: "memory");
        }
        __syncthreads();
        uint32_t aB = sb + OFF_A(it & 1);
        uint32_t bB = sb + OFF_B(it & 1);
        #pragma unroll
        for (int kk = 0; kk < 4; kk++) {
            uint32_t afr[2][4], bfr[4][4];
            #pragma unroll
            for (int mt = 0; mt < 2; mt++) {
                int r = warp * 32 + mt * 16 + (lane & 15);
                int c = kk * 2 + (lane >> 4);
                int sw = c ^ (r & 7);
                ldsm_x4(afr[mt], aB + r * 128 + sw * 16);
            }
            #pragma unroll
            for (int nb = 0; nb < 4; nb++) {
                int r = nb * 16 + ((lane >> 4) << 3) + (lane & 7);
                int c = kk * 2 + ((lane >> 3) & 1);
                int sw = c ^ (r & 7);
                ldsm_x4(bfr[nb], bB + r * 128 + sw * 16);
            }
            #pragma unroll
            for (int mt = 0; mt < 2; mt++)
                #pragma unroll
                for (int nt = 0; nt < 8; nt++)
                    mma16816(acc[mt][nt], afr[mt], &bfr[nt >> 1][(nt & 1) * 2]);
        }
        __syncthreads();
    }

    // ---- epilogue ----
    int gr = lane >> 2, gc = lane & 3;
    #pragma unroll
    for (int mt = 0; mt < 2; mt++) {
        #pragma unroll
        for (int half = 0; half < 2; half++) {
            int row = row0 + warp * 32 + mt * 16 + gr + half * 8;
            size_t orow = row;
            if (MODE == 3) {
                int w = row / 49, n = row - w * 49;
                int bb = w >> 6, rem = w & 63, hb = rem >> 3, wb = rem & 7;
                int r = n / 7, cn = n - r * 7;
                int hh = hb * 7 + r + 3;  if (hh >= 56) hh -= 56;
                int ww = wb * 7 + cn + 3; if (ww >= 56) ww -= 56;
                orow = ((size_t)bb * 3136 + hh * 56 + ww);
            }
            #pragma unroll
            for (int nt = 0; nt < 8; nt++) {
                int col = col0 + nt * 8 + gc * 2;
                float v0 = acc[mt][nt][half * 2 + 0] + bias[col];
                float v1 = acc[mt][nt][half * 2 + 1] + bias[col + 1];
                if (MODE == 1) {
                    v0 = 0.5f * v0 * (1.f + erff(v0 * 0.70710678118654752f));
                    v1 = 0.5f * v1 * (1.f + erff(v1 * 0.70710678118654752f));
                } else if (MODE == 2) {
                    const float* ap = aux + (size_t)row * N + col;
                    v0 += ap[0]; v1 += ap[1];
                } else if (MODE == 3) {
                    const float* ap = aux + orow * CD + col;
                    v0 += ap[0]; v1 += ap[1];
                }
                if (sizeof(OutT) == 2) {
                    *(uint32_t*)((bf16*)Cout + (size_t)row * N + col) = packbf(v0, v1);
                } else if (MODE == 3) {
                    *(float2*)((float*)Cout + orow * CD + col) = make_float2(v0, v1);
                } else {
                    *(float2*)((float*)Cout + (size_t)row * N + col) = make_float2(v0, v1);
                }
            }
        }
    }
}

// ---------------- MMA attention: block = (window, head pair) ----------------
__global__ __launch_bounds__(256)
void attn_mma(const bf16* __restrict__ qkv,
              const float* __restrict__ bias6,
              bf16* __restrict__ out)
{
    int win = blockIdx.y;
    int hp  = blockIdx.x;
    int tid = threadIdx.x;
    int wg  = tid >> 7;
    int h   = hp * 2 + wg;
    int wgtid = tid & 127;
    int warp  = wgtid >> 5;
    int lane  = tid & 31;

    __shared__ __align__(16) bf16 Qs[2][64 * 32];
    __shared__ __align__(16) bf16 Ks[2][64 * 32];
    __shared__ __align__(16) bf16 Vs[2][64 * 32];

    uint32_t qb = smem_u32(&Qs[wg][0]);
    uint32_t kb = smem_u32(&Ks[wg][0]);
    uint32_t vb = smem_u32(&Vs[wg][0]);

    const bf16* src = qkv + (size_t)win * 49 * 576 + h * HDIM;
    for (int i = wgtid; i < 256; i += 128) {
        int row = i >> 2, c = i & 3;
        int sw = c ^ ((row >> 1) & 3);
        int sz = (row < 49) ? 16 : 0;
        const bf16* s = (row < 49) ? (src + (size_t)row * 576 + c * 8) : src;
        cp16z(qb + (row * 4 + sw) * 16, s, sz);
        cp16z(kb + (row * 4 + sw) * 16, s + CD, sz);
        cp16z(vb + (row * 4 + sw) * 16, s + 2 * CD, sz);
    }
    asm volatile("cp.async.commit_group;\n" ::: "memory");
    asm volatile("cp.async.wait_group 0;\n" ::: "memory");
    __syncthreads();

    float sacc[8][4];
    #pragma unroll
    for (int t = 0; t < 8; t++)
        #pragma unroll
        for (int i = 0; i < 4; i++) sacc[t][i] = 0.f;

    #pragma unroll
    for (int kk = 0; kk < 2; kk++) {
        uint32_t afr[4], bfr[4][4];
        {
            int r = warp * 16 + (lane & 15);
            int c = kk * 2 + (lane >> 4);
            int sw = c ^ ((r >> 1) & 3);
            ldsm_x4(afr, qb + (r * 4 + sw) * 16);
        }
        #pragma unroll
        for (int nb = 0; nb < 4; nb++) {
            int r = nb * 16 + ((lane >> 4) << 3) + (lane & 7);
            int c = kk * 2 + ((lane >> 3) & 1);
            int sw = c ^ ((r >> 1) & 3);
            ldsm_x4(bfr[nb], kb + (r * 4 + sw) * 16);
        }
        #pragma unroll
        for (int nt = 0; nt < 8; nt++)
            mma16816(sacc[nt], afr, &bfr[nt >> 1][(nt & 1) * 2]);
    }

    const float scale = 0.17677669529663687f;
    int gr = lane >> 2, gc2 = (lane & 3) * 2;
    int rbase = warp * 16 + gr;
    float mx[2] = {-1e30f, -1e30f}, sum[2] = {0.f, 0.f}, inv[2];

    #pragma unroll
    for (int half = 0; half < 2; half++) {
        int row = rbase + half * 8;
        int rc = (row < 49) ? row : 48;
        const float* bp = bias6 + ((size_t)h * 49 + rc) * 49;
        #pragma unroll
        for (int nt = 0; nt < 8; nt++) {
            #pragma unroll
            for (int j = 0; j < 2; j++) {
                int col = nt * 8 + gc2 + j;
                float v = sacc[nt][half * 2 + j] * scale;
                v = (col < 49 && row < 49) ? (v + bp[(col < 49) ? col : 48]) : -1e30f;
                sacc[nt][half * 2 + j] = v;
                mx[half] = fmaxf(mx[half], v);
            }
        }
        mx[half] = fmaxf(mx[half], __shfl_xor_sync(0xFFFFFFFFu, mx[half], 1));
        mx[half] = fmaxf(mx[half], __shfl_xor_sync(0xFFFFFFFFu, mx[half], 2));
        #pragma unroll
        for (int nt = 0; nt < 8; nt++) {
            #pragma unroll
            for (int j = 0; j < 2; j++) {
                float e = __expf(sacc[nt][half * 2 + j] - mx[half]);
                sacc[nt][half * 2 + j] = e;
                sum[half] += e;
            }
        }
        sum[half] += __shfl_xor_sync(0xFFFFFFFFu, sum[half], 1);
        sum[half] += __shfl_xor_sync(0xFFFFFFFFu, sum[half], 2);
        inv[half] = 1.f / sum[half];
    }

    uint32_t pfr[4][4];
    #pragma unroll
    for (int ks = 0; ks < 4; ks++) {
        int t0 = 2 * ks, t1 = t0 + 1;
        pfr[ks][0] = packbf(sacc[t0][0], sacc[t0][1]);
        pfr[ks][1] = packbf(sacc[t0][2], sacc[t0][3]);
        pfr[ks][2] = packbf(sacc[t1][0], sacc[t1][1]);
        pfr[ks][3] = packbf(sacc[t1][2], sacc[t1][3]);
    }

    float oacc[4][4];
    #pragma unroll
    for (int t = 0; t < 4; t++)
        #pragma unroll
        for (int i = 0; i < 4; i++) oacc[t][i] = 0.f;

    #pragma unroll
    for (int ks = 0; ks < 4; ks++) {
        uint32_t vfr[2][4];
        #pragma unroll
        for (int nb = 0; nb < 2; nb++) {
            int r = ks * 16 + ((lane >> 3) & 1) * 8 + (lane & 7);
            int c = nb * 2 + (lane >> 4);
            int sw = c ^ ((r >> 1) & 3);
            ldsm_x4t(vfr[nb], vb + (r * 4 + sw) * 16);
        }
        #pragma unroll
        for (int nt = 0; nt < 4; nt++)
            mma16816(oacc[nt], pfr[ks], &vfr[nt >> 1][(nt & 1) * 2]);
    }

    bf16* ob = out + (size_t)win * 49 * CD + h * HDIM;
    #pragma unroll
    for (int half = 0; half < 2; half++) {
        int row = rbase + half * 8;
        if (row < 49) {
            #pragma unroll
            for (int nt = 0; nt < 4; nt++) {
                int col = nt * 8 + gc2;
                __nv_bfloat162 o = __floats2bfloat162_rn(oacc[nt][half * 2] * inv[half],
                                                         oacc[nt][half * 2 + 1] * inv[half]);
                *(__nv_bfloat162*)(ob + (size_t)row * CD + col) = o;
            }
        }
    }
}

// ---------------- launch ----------------------------------------------------
extern "C" void kernel_launch(void* const* d_in, const int* in_sizes, int n_in,
                              void* d_out, int out_size)
{
    const float* x    = (const float*)d_in[0];
    const float* n1g  = (const float*)d_in[1];
    const float* n1b  = (const float*)d_in[2];
    const float* qkvw = (const float*)d_in[3];
    const float* qkvb = (const float*)d_in[4];
    const float* pw   = (const float*)d_in[5];
    const float* pb   = (const float*)d_in[6];
    const float* tab  = (const float*)d_in[7];
    const float* n2g  = (const float*)d_in[8];
    const float* n2b  = (const float*)d_in[9];
    const float* f1w  = (const float*)d_in[10];
    const float* f1b  = (const float*)d_in[11];
    const float* f2w  = (const float*)d_in[12];
    const float* f2b  = (const float*)d_in[13];
    const int*   ridx = (const int*)  d_in[14];

    bf16 *p_xwb, *p_qkvb, *p_attb, *p_xn2b, *p_hb;
    float *p_x2, *p_bias6;
    bf16 *p_wqkv, *p_wp, *p_wf1, *p_wf2;
    cudaGetSymbolAddress((void**)&p_xwb,  g_xwb);
    cudaGetSymbolAddress((void**)&p_qkvb, g_qkvb);
    cudaGetSymbolAddress((void**)&p_attb, g_attb);
    cudaGetSymbolAddress((void**)&p_x2,   g_x2);
    cudaGetSymbolAddress((void**)&p_xn2b, g_xn2b);
    cudaGetSymbolAddress((void**)&p_hb,   g_hb);
    cudaGetSymbolAddress((void**)&p_wqkv, g_wqkv);
    cudaGetSymbolAddress((void**)&p_wp,   g_wp);
    cudaGetSymbolAddress((void**)&p_wf1,  g_wf1);
    cudaGetSymbolAddress((void**)&p_wf2,  g_wf2);
    cudaGetSymbolAddress((void**)&p_bias6, g_bias6);

    cudaFuncSetAttribute(gemm_s128<0, bf16>,  cudaFuncAttributeMaxDynamicSharedMemorySize, GSM_TOT);
    cudaFuncSetAttribute(gemm_s128<1, bf16>,  cudaFuncAttributeMaxDynamicSharedMemorySize, GSM_TOT);
    cudaFuncSetAttribute(gemm_s128<2, float>, cudaFuncAttributeMaxDynamicSharedMemorySize, GSM_TOT);
    cudaFuncSetAttribute(gemm_s128<3, float>, cudaFuncAttributeMaxDynamicSharedMemorySize, GSM_TOT);

    // 1. LN1 + shift + window partition, fused with weight prep
    ln1_prep_kernel<<<LN1_BLOCKS + PREP_BLOCKS, 256>>>(
        x, n1g, n1b, p_xwb, qkvw, pw, f1w, f2w, tab, ridx);
    // 2. QKV GEMM -> bf16
    gemm_s128<0, bf16><<<dim3(576 / GBN, TOK / GBM), NTH, GSM_TOT>>>(
        p_xwb, p_wqkv, qkvb, nullptr, p_qkvb, 576, CD);
    // 3. attention (tensor cores)
    attn_mma<<<dim3(3, NWIN), 256>>>(p_qkvb, p_bias6, p_attb);
    // 4. proj GEMM + reverse/unshift scatter + residual(x) -> x2
    gemm_s128<3, float><<<dim3(CD / GBN, TOK / GBM), NTH, GSM_TOT>>>(
        p_attb, p_wp, pb, x, p_x2, CD, CD);
    // 5. LN2
    ln_warp2<<<TOK / 8, 256>>>(p_x2, n2g, n2b, p_xn2b);
    // 6. FC1 + GELU
    gemm_s128<1, bf16><<<dim3(HID / GBN, TOK / GBM), NTH, GSM_TOT>>>(
        p_xn2b, p_wf1, f1b, nullptr, p_hb, HID, CD);
    // 7. FC2 + residual(x2) -> d_out
    gemm_s128<2, float><<<dim3(CD / GBN, TOK / GBM), NTH, GSM_TOT>>>(
        p_hb, p_wf2, f2b, p_x2, (float*)d_out, CD, HID);
}

// round 16
// speedup vs baseline: 1.2320x; 1.0557x over previous
#include <cuda_runtime.h>
#include <cuda_bf16.h>
#include <math.h>
#include <stdint.h>

#define TOK   100352
#define CD    192
#define NWIN  2048
#define NHEAD 6
#define HDIM  32
#define HID   768

typedef __nv_bfloat16 bf16;

// ---------------- scratch ----------------------------------------------------
__device__ bf16  g_xwb [(size_t)TOK * CD];
__device__ bf16  g_qkvb[(size_t)TOK * 3 * CD];
__device__ bf16  g_attb[(size_t)TOK * CD];
__device__ float g_x2  [(size_t)TOK * CD];
__device__ bf16  g_xn2b[(size_t)TOK * CD];
__device__ bf16  g_hb  [(size_t)TOK * HID];
__device__ bf16  g_wqkv[576 * CD];
__device__ bf16  g_wp  [CD * CD];
__device__ bf16  g_wf1 [HID * CD];
__device__ bf16  g_wf2 [CD * HID];
__device__ float g_bias6[NHEAD * 49 * 49];

#define N_QKVW (576 * CD)
#define N_PW   (CD * CD)
#define N_F1W  (HID * CD)
#define N_F2W  (CD * HID)
#define N_WTOT (N_QKVW + N_PW + N_F1W + N_F2W)
#define N_BIAS (NHEAD * 49 * 49)
#define LN1_BLOCKS (TOK / 8)
#define PREP_BLOCKS ((N_WTOT + N_BIAS + 255) / 256)

// ---------------- fused LN1(+shift+gather) AND weight prep ------------------
__global__ __launch_bounds__(256)
void ln1_prep_kernel(const float* __restrict__ xin,
                     const float* __restrict__ gamma,
                     const float* __restrict__ beta,
                     bf16* __restrict__ out,
                     const float* __restrict__ qkvw, const float* __restrict__ pw,
                     const float* __restrict__ f1w, const float* __restrict__ f2w,
                     const float* __restrict__ tab, const int* __restrict__ ridx)
{
    if (blockIdx.x >= LN1_BLOCKS) {
        int i = (blockIdx.x - LN1_BLOCKS) * 256 + threadIdx.x;
        if (i < N_QKVW) { g_wqkv[i] = __float2bfloat16(qkvw[i]); return; }
        i -= N_QKVW;
        if (i < N_PW)   { g_wp[i]   = __float2bfloat16(pw[i]);   return; }
        i -= N_PW;
        if (i < N_F1W)  { g_wf1[i]  = __float2bfloat16(f1w[i]);  return; }
        i -= N_F1W;
        if (i < N_F2W)  { g_wf2[i]  = __float2bfloat16(f2w[i]);  return; }
        i -= N_F2W;
        if (i < N_BIAS) {
            int h = i / 2401, nm = i - h * 2401;
            g_bias6[i] = tab[ridx[nm] * NHEAD + h];
        }
        return;
    }
    int m = blockIdx.x * 8 + (threadIdx.x >> 5);
    int lane = threadIdx.x & 31;
    int w = m / 49, n = m - w * 49;
    int bb = w >> 6, rem = w & 63, hb = rem >> 3, wb = rem & 7;
    int r = n / 7, cn = n - r * 7;
    int hh = hb * 7 + r + 3;  if (hh >= 56) hh -= 56;
    int ww = wb * 7 + cn + 3; if (ww >= 56) ww -= 56;
    size_t src = ((size_t)bb * 3136 + hh * 56 + ww);

    const float* p = xin + src * CD;
    float v[6];
    float s = 0.f, s2 = 0.f;
    #pragma unroll
    for (int i = 0; i < 6; i++) {
        v[i] = p[lane + 32 * i];
        s += v[i]; s2 += v[i] * v[i];
    }
    #pragma unroll
    for (int o = 16; o > 0; o >>= 1) {
        s  += __shfl_xor_sync(0xFFFFFFFFu, s,  o);
        s2 += __shfl_xor_sync(0xFFFFFFFFu, s2, o);
    }
    float mean = s * (1.f / CD);
    float var  = s2 * (1.f / CD) - mean * mean;
    float inv  = rsqrtf(var + 1e-5f);
    bf16* o = out + (size_t)m * CD;
    #pragma unroll
    for (int i = 0; i < 6; i++) {
        int c = lane + 32 * i;
        o[c] = __float2bfloat16((v[i] - mean) * inv * gamma[c] + beta[c]);
    }
}

// ---------------- LayerNorm (plain, for LN2): one warp per token ------------
__global__ __launch_bounds__(256)
void ln_warp2(const float* __restrict__ xin,
              const float* __restrict__ gamma,
              const float* __restrict__ beta,
              bf16* __restrict__ out)
{
    int m = blockIdx.x * 8 + (threadIdx.x >> 5);
    int lane = threadIdx.x & 31;
    const float* p = xin + (size_t)m * CD;
    float v[6];
    float s = 0.f, s2 = 0.f;
    #pragma unroll
    for (int i = 0; i < 6; i++) {
        v[i] = p[lane + 32 * i];
        s += v[i]; s2 += v[i] * v[i];
    }
    #pragma unroll
    for (int o = 16; o > 0; o >>= 1) {
        s  += __shfl_xor_sync(0xFFFFFFFFu, s,  o);
        s2 += __shfl_xor_sync(0xFFFFFFFFu, s2, o);
    }
    float mean = s * (1.f / CD);
    float var  = s2 * (1.f / CD) - mean * mean;
    float inv  = rsqrtf(var + 1e-5f);
    bf16* o = out + (size_t)m * CD;
    #pragma unroll
    for (int i = 0; i < 6; i++) {
        int c = lane + 32 * i;
        o[c] = __float2bfloat16((v[i] - mean) * inv * gamma[c] + beta[c]);
    }
}

// ---------------- helpers ----------------------------------------------------
__device__ __forceinline__ void cp16(uint32_t dst, const void* src) {
    asm volatile("cp.async.cg.shared.global [%0], [%1], 16;\n" :: "r"(dst), "l"(src));
}
__device__ __forceinline__ void cp16z(uint32_t dst, const void* src, int sz) {
    asm volatile("cp.async.cg.shared.global [%0], [%1], 16, %2;\n" :: "r"(dst), "l"(src), "r"(sz));
}
__device__ __forceinline__ void ldsm_x4(uint32_t* r, uint32_t addr) {
    asm volatile("ldmatrix.sync.aligned.m8n8.x4.shared.b16 {%0,%1,%2,%3}, [%4];\n"
                 : "=r"(r[0]), "=r"(r[1]), "=r"(r[2]), "=r"(r[3]) : "r"(addr));
}
__device__ __forceinline__ void ldsm_x4t(uint32_t* r, uint32_t addr) {
    asm volatile("ldmatrix.sync.aligned.m8n8.x4.trans.shared.b16 {%0,%1,%2,%3}, [%4];\n"
                 : "=r"(r[0]), "=r"(r[1]), "=r"(r[2]), "=r"(r[3]) : "r"(addr));
}
__device__ __forceinline__ void mma16816(float* d, const uint32_t* a, const uint32_t* b) {
    asm volatile(
        "mma.sync.aligned.m16n8k16.row.col.f32.bf16.bf16.f32 "
        "{%0,%1,%2,%3}, {%4,%5,%6,%7}, {%8,%9}, {%0,%1,%2,%3};\n"
        : "+f"(d[0]), "+f"(d[1]), "+f"(d[2]), "+f"(d[3])
        : "r"(a[0]), "r"(a[1]), "r"(a[2]), "r"(a[3]), "r"(b[0]), "r"(b[1]));
}
__device__ __forceinline__ uint32_t packbf(float a, float b) {
    __nv_bfloat162 t = __floats2bfloat162_rn(a, b);
    return *(uint32_t*)&t;
}
__device__ __forceinline__ uint32_t smem_u32(const void* p) {
    return (uint32_t)__cvta_generic_to_shared(p);
}

// ---------------- shared epilogue --------------------------------------------
template <int MODE, typename OutT>
__device__ __forceinline__ void gemm_epilogue(
    float acc[2][8][4], int row0, int col0, int warp, int lane,
    const float* __restrict__ bias, const float* __restrict__ aux,
    OutT* __restrict__ Cout, int N)
{
    int gr = lane >> 2, gc = lane & 3;
    #pragma unroll
    for (int mt = 0; mt < 2; mt++) {
        #pragma unroll
        for (int half = 0; half < 2; half++) {
            int row = row0 + warp * 32 + mt * 16 + gr + half * 8;
            size_t orow = row;
            if (MODE == 3) {
                int w = row / 49, n = row - w * 49;
                int bb = w >> 6, rem = w & 63, hb = rem >> 3, wb = rem & 7;
                int r = n / 7, cn = n - r * 7;
                int hh = hb * 7 + r + 3;  if (hh >= 56) hh -= 56;
                int ww = wb * 7 + cn + 3; if (ww >= 56) ww -= 56;
                orow = ((size_t)bb * 3136 + hh * 56 + ww);
            }
            #pragma unroll
            for (int nt = 0; nt < 8; nt++) {
                int col = col0 + nt * 8 + gc * 2;
                float v0 = acc[mt][nt][half * 2 + 0] + bias[col];
                float v1 = acc[mt][nt][half * 2 + 1] + bias[col + 1];
                if (MODE == 1) {
                    v0 = 0.5f * v0 * (1.f + erff(v0 * 0.70710678118654752f));
                    v1 = 0.5f * v1 * (1.f + erff(v1 * 0.70710678118654752f));
                } else if (MODE == 2) {
                    const float* ap = aux + (size_t)row * N + col;
                    v0 += ap[0]; v1 += ap[1];
                } else if (MODE == 3) {
                    const float* ap = aux + orow * CD + col;
                    v0 += ap[0]; v1 += ap[1];
                }
                if (sizeof(OutT) == 2) {
                    *(uint32_t*)((bf16*)Cout + (size_t)row * N + col) = packbf(v0, v1);
                } else if (MODE == 3) {
                    *(float2*)((float*)Cout + orow * CD + col) = make_float2(v0, v1);
                } else {
                    *(float2*)((float*)Cout + (size_t)row * N + col) = make_float2(v0, v1);
                }
            }
        }
    }
}

// ---------------- "load-all" GEMM for K=192 ----------------------------------
// BM=128, BN=64, K=192 fully resident in smem (3 panels of 64 cols each).
// 128 threads, 4 warps along M, warp tile 32x64.
// ONE cp.async wait + ONE __syncthreads; then 12 (6 LDSM + 16 MMA) groups
// with zero barriers. 3 CTAs/SM (smem 72KB), 170-reg budget for scheduling.
#define FBM 128
#define FBN 64
#define F_SA 16384             // one A panel: 128 rows * 128B
#define F_SB 8192              // one B panel: 64 rows * 128B
#define F_OFF_A(p) ((p) * F_SA)
#define F_OFF_B(p) (3 * F_SA + (p) * F_SB)
#define F_SM_TOT (3 * F_SA + 3 * F_SB)         // 73728

template <int MODE, typename OutT>
__global__ __launch_bounds__(128, 3)
void gemm_full192(const bf16* __restrict__ A, const bf16* __restrict__ B,
                  const float* __restrict__ bias, const float* __restrict__ aux,
                  OutT* __restrict__ Cout, int N)
{
    extern __shared__ __align__(128) char smem[];
    uint32_t sb = smem_u32(smem);

    int tid = threadIdx.x;
    int warp = tid >> 5, lane = tid & 31;
    int row0 = blockIdx.y * FBM;
    int col0 = blockIdx.x * FBN;

    // ---- stage ALL of A (128x192) and B (64x192) ----
    #pragma unroll
    for (int j = 0; j < 24; j++) {                 // A: 3072 chunks of 16B
        int idx = tid + j * 128;
        int p = idx >> 10;                         // panel 0..2
        int wi = idx & 1023;
        int r = wi >> 3, c = wi & 7;
        int sw = c ^ (r & 7);
        cp16(sb + F_OFF_A(p) + r * 128 + sw * 16,
             A + (size_t)(row0 + r) * CD + p * 64 + c * 8);
    }
    #pragma unroll
    for (int j = 0; j < 12; j++) {                 // B: 1536 chunks
        int idx = tid + j * 128;
        int p = idx >> 9;
        int wi = idx & 511;
        int r = wi >> 3, c = wi & 7;
        int sw = c ^ (r & 7);
        cp16(sb + F_OFF_B(p) + r * 128 + sw * 16,
             B + (size_t)(col0 + r) * CD + p * 64 + c * 8);
    }
    asm volatile("cp.async.commit_group;\n" ::: "memory");

    float acc[2][8][4];
    #pragma unroll
    for (int mt = 0; mt < 2; mt++)
        #pragma unroll
        for (int nt = 0; nt < 8; nt++)
            #pragma unroll
            for (int i = 0; i < 4; i++) acc[mt][nt][i] = 0.f;

    asm volatile("cp.async.wait_group 0;\n" ::: "memory");
    __syncthreads();

    // ---- barrier-free mainloop: 3 panels x 4 kk ----
    #pragma unroll
    for (int p = 0; p < 3; p++) {
        uint32_t aB = sb + F_OFF_A(p);
        uint32_t bB = sb + F_OFF_B(p);
        #pragma unroll
        for (int kk = 0; kk < 4; kk++) {
            uint32_t afr[2][4], bfr[4][4];
            #pragma unroll
            for (int mt = 0; mt < 2; mt++) {
                int r = warp * 32 + mt * 16 + (lane & 15);
                int c = kk * 2 + (lane >> 4);
                int sw = c ^ (r & 7);
                ldsm_x4(afr[mt], aB + r * 128 + sw * 16);
            }
            #pragma unroll
            for (int nb = 0; nb < 4; nb++) {
                int r = nb * 16 + ((lane >> 4) << 3) + (lane & 7);
                int c = kk * 2 + ((lane >> 3) & 1);
                int sw = c ^ (r & 7);
                ldsm_x4(bfr[nb], bB + r * 128 + sw * 16);
            }
            #pragma unroll
            for (int mt = 0; mt < 2; mt++)
                #pragma unroll
                for (int nt = 0; nt < 8; nt++)
                    mma16816(acc[mt][nt], afr[mt], &bfr[nt >> 1][(nt & 1) * 2]);
        }
    }

    gemm_epilogue<MODE, OutT>(acc, row0, col0, warp, lane, bias, aux, Cout, N);
}

// ---------------- pipelined GEMM (fc2, K=768) --------------------------------
#define GBM 128
#define GBN 64
#define GBK 64
#define NTH 128
#define SA_STG 16384
#define SB_STG 8192
#define OFF_A(s) ((s) * SA_STG)
#define OFF_B(s) (2 * SA_STG + (s) * SB_STG)
#define GSM_TOT  (2 * SA_STG + 2 * SB_STG)     // 49152

template <int MODE, typename OutT>
__global__ __launch_bounds__(NTH, 4)
void gemm_s128(const bf16* __restrict__ A, const bf16* __restrict__ B,
               const float* __restrict__ bias, const float* __restrict__ aux,
               OutT* __restrict__ Cout, int N, int K)
{
    extern __shared__ __align__(128) char smem[];
    uint32_t sb = smem_u32(smem);

    int tid = threadIdx.x;
    int warp = tid >> 5, lane = tid & 31;
    int row0 = blockIdx.y * GBM;
    int col0 = blockIdx.x * GBN;

    float acc[2][8][4];
    #pragma unroll
    for (int mt = 0; mt < 2; mt++)
        #pragma unroll
        for (int nt = 0; nt < 8; nt++)
            #pragma unroll
            for (int i = 0; i < 4; i++) acc[mt][nt][i] = 0.f;

    const int nk = K / GBK;

    auto stage = [&](int s, int k0) {
        #pragma unroll
        for (int j = 0; j < 8; j++) {
            int idx = tid + j * NTH;
            int r = idx >> 3, c = idx & 7;
            int sw = c ^ (r & 7);
            cp16(sb + OFF_A(s) + r * 128 + sw * 16,
                 A + (size_t)(row0 + r) * K + k0 + c * 8);
        }
        #pragma unroll
        for (int j = 0; j < 4; j++) {
            int idx = tid + j * NTH;
            int r = idx >> 3, c = idx & 7;
            int sw = c ^ (r & 7);
            cp16(sb + OFF_B(s) + r * 128 + sw * 16,
                 B + (size_t)(col0 + r) * K + k0 + c * 8);
        }
        asm volatile("cp.async.commit_group;\n" ::: "memory");
    };

    stage(0, 0);

    for (int it = 0; it < nk; it++) {
        if (it + 1 < nk) {
            stage((it + 1) & 1, (it + 1) * GBK);
            asm volatile("cp.async.wait_group 1;\n" ::: "memory");
        } else {
            asm volatile("cp.async.wait_group 0;\n" ::: "memory");
        }
        __syncthreads();
        uint32_t aB = sb + OFF_A(it & 1);
        uint32_t bB = sb + OFF_B(it & 1);
        #pragma unroll
        for (int kk = 0; kk < 4; kk++) {
            uint32_t afr[2][4], bfr[4][4];
            #pragma unroll
            for (int mt = 0; mt < 2; mt++) {
                int r = warp * 32 + mt * 16 + (lane & 15);
                int c = kk * 2 + (lane >> 4);
                int sw = c ^ (r & 7);
                ldsm_x4(afr[mt], aB + r * 128 + sw * 16);
            }
            #pragma unroll
            for (int nb = 0; nb < 4; nb++) {
                int r = nb * 16 + ((lane >> 4) << 3) + (lane & 7);
                int c = kk * 2 + ((lane >> 3) & 1);
                int sw = c ^ (r & 7);
                ldsm_x4(bfr[nb], bB + r * 128 + sw * 16);
            }
            #pragma unroll
            for (int mt = 0; mt < 2; mt++)
                #pragma unroll
                for (int nt = 0; nt < 8; nt++)
                    mma16816(acc[mt][nt], afr[mt], &bfr[nt >> 1][(nt & 1) * 2]);
        }
        __syncthreads();
    }

    gemm_epilogue<MODE, OutT>(acc, row0, col0, warp, lane, bias, aux, Cout, N);
}

// ---------------- MMA attention: block = (window, head pair) ----------------
__global__ __launch_bounds__(256)
void attn_mma(const bf16* __restrict__ qkv,
              const float* __restrict__ bias6,
              bf16* __restrict__ out)
{
    int win = blockIdx.y;
    int hp  = blockIdx.x;
    int tid = threadIdx.x;
    int wg  = tid >> 7;
    int h   = hp * 2 + wg;
    int wgtid = tid & 127;
    int warp  = wgtid >> 5;
    int lane  = tid & 31;

    __shared__ __align__(16) bf16 Qs[2][64 * 32];
    __shared__ __align__(16) bf16 Ks[2][64 * 32];
    __shared__ __align__(16) bf16 Vs[2][64 * 32];

    uint32_t qb = smem_u32(&Qs[wg][0]);
    uint32_t kb = smem_u32(&Ks[wg][0]);
    uint32_t vb = smem_u32(&Vs[wg][0]);

    const bf16* src = qkv + (size_t)win * 49 * 576 + h * HDIM;
    for (int i = wgtid; i < 256; i += 128) {
        int row = i >> 2, c = i & 3;
        int sw = c ^ ((row >> 1) & 3);
        int sz = (row < 49) ? 16 : 0;
        const bf16* s = (row < 49) ? (src + (size_t)row * 576 + c * 8) : src;
        cp16z(qb + (row * 4 + sw) * 16, s, sz);
        cp16z(kb + (row * 4 + sw) * 16, s + CD, sz);
        cp16z(vb + (row * 4 + sw) * 16, s + 2 * CD, sz);
    }
    asm volatile("cp.async.commit_group;\n" ::: "memory");
    asm volatile("cp.async.wait_group 0;\n" ::: "memory");
    __syncthreads();

    float sacc[8][4];
    #pragma unroll
    for (int t = 0; t < 8; t++)
        #pragma unroll
        for (int i = 0; i < 4; i++) sacc[t][i] = 0.f;

    #pragma unroll
    for (int kk = 0; kk < 2; kk++) {
        uint32_t afr[4], bfr[4][4];
        {
            int r = warp * 16 + (lane & 15);
            int c = kk * 2 + (lane >> 4);
            int sw = c ^ ((r >> 1) & 3);
            ldsm_x4(afr, qb + (r * 4 + sw) * 16);
        }
        #pragma unroll
        for (int nb = 0; nb < 4; nb++) {
            int r = nb * 16 + ((lane >> 4) << 3) + (lane & 7);
            int c = kk * 2 + ((lane >> 3) & 1);
            int sw = c ^ ((r >> 1) & 3);
            ldsm_x4(bfr[nb], kb + (r * 4 + sw) * 16);
        }
        #pragma unroll
        for (int nt = 0; nt < 8; nt++)
            mma16816(sacc[nt], afr, &bfr[nt >> 1][(nt & 1) * 2]);
    }

    const float scale = 0.17677669529663687f;
    int gr = lane >> 2, gc2 = (lane & 3) * 2;
    int rbase = warp * 16 + gr;
    float mx[2] = {-1e30f, -1e30f}, sum[2] = {0.f, 0.f}, inv[2];

    #pragma unroll
    for (int half = 0; half < 2; half++) {
        int row = rbase + half * 8;
        int rc = (row < 49) ? row : 48;
        const float* bp = bias6 + ((size_t)h * 49 + rc) * 49;
        #pragma unroll
        for (int nt = 0; nt < 8; nt++) {
            #pragma unroll
            for (int j = 0; j < 2; j++) {
                int col = nt * 8 + gc2 + j;
                float v = sacc[nt][half * 2 + j] * scale;
                v = (col < 49 && row < 49) ? (v + bp[(col < 49) ? col : 48]) : -1e30f;
                sacc[nt][half * 2 + j] = v;
                mx[half] = fmaxf(mx[half], v);
            }
        }
        mx[half] = fmaxf(mx[half], __shfl_xor_sync(0xFFFFFFFFu, mx[half], 1));
        mx[half] = fmaxf(mx[half], __shfl_xor_sync(0xFFFFFFFFu, mx[half], 2));
        #pragma unroll
        for (int nt = 0; nt < 8; nt++) {
            #pragma unroll
            for (int j = 0; j < 2; j++) {
                float e = __expf(sacc[nt][half * 2 + j] - mx[half]);
                sacc[nt][half * 2 + j] = e;
                sum[half] += e;
            }
        }
        sum[half] += __shfl_xor_sync(0xFFFFFFFFu, sum[half], 1);
        sum[half] += __shfl_xor_sync(0xFFFFFFFFu, sum[half], 2);
        inv[half] = 1.f / sum[half];
    }

    uint32_t pfr[4][4];
    #pragma unroll
    for (int ks = 0; ks < 4; ks++) {
        int t0 = 2 * ks, t1 = t0 + 1;
        pfr[ks][0] = packbf(sacc[t0][0], sacc[t0][1]);
        pfr[ks][1] = packbf(sacc[t0][2], sacc[t0][3]);
        pfr[ks][2] = packbf(sacc[t1][0], sacc[t1][1]);
        pfr[ks][3] = packbf(sacc[t1][2], sacc[t1][3]);
    }

    float oacc[4][4];
    #pragma unroll
    for (int t = 0; t < 4; t++)
        #pragma unroll
        for (int i = 0; i < 4; i++) oacc[t][i] = 0.f;

    #pragma unroll
    for (int ks = 0; ks < 4; ks++) {
        uint32_t vfr[2][4];
        #pragma unroll
        for (int nb = 0; nb < 2; nb++) {
            int r = ks * 16 + ((lane >> 3) & 1) * 8 + (lane & 7);
            int c = nb * 2 + (lane >> 4);
            int sw = c ^ ((r >> 1) & 3);
            ldsm_x4t(vfr[nb], vb + (r * 4 + sw) * 16);
        }
        #pragma unroll
        for (int nt = 0; nt < 4; nt++)
            mma16816(oacc[nt], pfr[ks], &vfr[nt >> 1][(nt & 1) * 2]);
    }

    bf16* ob = out + (size_t)win * 49 * CD + h * HDIM;
    #pragma unroll
    for (int half = 0; half < 2; half++) {
        int row = rbase + half * 8;
        if (row < 49) {
            #pragma unroll
            for (int nt = 0; nt < 4; nt++) {
                int col = nt * 8 + gc2;
                __nv_bfloat162 o = __floats2bfloat162_rn(oacc[nt][half * 2] * inv[half],
                                                         oacc[nt][half * 2 + 1] * inv[half]);
                *(__nv_bfloat162*)(ob + (size_t)row * CD + col) = o;
            }
        }
    }
}

// ---------------- launch ----------------------------------------------------
extern "C" void kernel_launch(void* const* d_in, const int* in_sizes, int n_in,
                              void* d_out, int out_size)
{
    const float* x    = (const float*)d_in[0];
    const float* n1g  = (const float*)d_in[1];
    const float* n1b  = (const float*)d_in[2];
    const float* qkvw = (const float*)d_in[3];
    const float* qkvb = (const float*)d_in[4];
    const float* pw   = (const float*)d_in[5];
    const float* pb   = (const float*)d_in[6];
    const float* tab  = (const float*)d_in[7];
    const float* n2g  = (const float*)d_in[8];
    const float* n2b  = (const float*)d_in[9];
    const float* f1w  = (const float*)d_in[10];
    const float* f1b  = (const float*)d_in[11];
    const float* f2w  = (const float*)d_in[12];
    const float* f2b  = (const float*)d_in[13];
    const int*   ridx = (const int*)  d_in[14];

    bf16 *p_xwb, *p_qkvb, *p_attb, *p_xn2b, *p_hb;
    float *p_x2, *p_bias6;
    bf16 *p_wqkv, *p_wp, *p_wf1, *p_wf2;
    cudaGetSymbolAddress((void**)&p_xwb,  g_xwb);
    cudaGetSymbolAddress((void**)&p_qkvb, g_qkvb);
    cudaGetSymbolAddress((void**)&p_attb, g_attb);
    cudaGetSymbolAddress((void**)&p_x2,   g_x2);
    cudaGetSymbolAddress((void**)&p_xn2b, g_xn2b);
    cudaGetSymbolAddress((void**)&p_hb,   g_hb);
    cudaGetSymbolAddress((void**)&p_wqkv, g_wqkv);
    cudaGetSymbolAddress((void**)&p_wp,   g_wp);
    cudaGetSymbolAddress((void**)&p_wf1,  g_wf1);
    cudaGetSymbolAddress((void**)&p_wf2,  g_wf2);
    cudaGetSymbolAddress((void**)&p_bias6, g_bias6);

    cudaFuncSetAttribute(gemm_full192<0, bf16>,  cudaFuncAttributeMaxDynamicSharedMemorySize, F_SM_TOT);
    cudaFuncSetAttribute(gemm_full192<1, bf16>,  cudaFuncAttributeMaxDynamicSharedMemorySize, F_SM_TOT);
    cudaFuncSetAttribute(gemm_full192<3, float>, cudaFuncAttributeMaxDynamicSharedMemorySize, F_SM_TOT);
    cudaFuncSetAttribute(gemm_s128<2, float>,    cudaFuncAttributeMaxDynamicSharedMemorySize, GSM_TOT);

    // 1. LN1 + shift + window partition, fused with weight prep
    ln1_prep_kernel<<<LN1_BLOCKS + PREP_BLOCKS, 256>>>(
        x, n1g, n1b, p_xwb, qkvw, pw, f1w, f2w, tab, ridx);
    // 2. QKV GEMM (K=192, load-all) -> bf16
    gemm_full192<0, bf16><<<dim3(576 / FBN, TOK / FBM), 128, F_SM_TOT>>>(
        p_xwb, p_wqkv, qkvb, nullptr, p_qkvb, 576);
    // 3. attention (tensor cores)
    attn_mma<<<dim3(3, NWIN), 256>>>(p_qkvb, p_bias6, p_attb);
    // 4. proj GEMM (K=192, load-all) + reverse/unshift scatter + residual(x) -> x2
    gemm_full192<3, float><<<dim3(CD / FBN, TOK / FBM), 128, F_SM_TOT>>>(
        p_attb, p_wp, pb, x, p_x2, CD);
    // 5. LN2
    ln_warp2<<<TOK / 8, 256>>>(p_x2, n2g, n2b, p_xn2b);
    // 6. FC1 + GELU (K=192, load-all)
    gemm_full192<1, bf16><<<dim3(HID / FBN, TOK / FBM), 128, F_SM_TOT>>>(
        p_xn2b, p_wf1, f1b, nullptr, p_hb, HID);
    // 7. FC2 + residual(x2) -> d_out (K=768, pipelined)
    gemm_s128<2, float><<<dim3(CD / GBN, TOK / GBM), NTH, GSM_TOT>>>(
        p_hb, p_wf2, f2b, p_x2, (float*)d_out, CD, HID);
}